// round 1
// baseline (speedup 1.0000x reference)
#include <cuda_runtime.h>
#include <cuda_bf16.h>
#include <math.h>

// ---------------------------------------------------------------------------
// Problem constants
// ---------------------------------------------------------------------------
#define B_   2
#define L_   2521
#define C_   2048
#define H_   16
#define HD_  128
#define M_   (B_ * L_)          // 5042
#define K_   2048
#define NQKV 6144

// cumulative scale-block ends (compile-time from SCALES)
__device__ __constant__ int d_cum[10] = {1, 5, 21, 57, 121, 265, 521, 921, 1497, 2521};

// ---------------------------------------------------------------------------
// Scratch (device globals; no allocation allowed)
// ---------------------------------------------------------------------------
__device__ float g_q[B_ * H_ * L_ * HD_];    // [bh][l][d]
__device__ float g_k[B_ * H_ * L_ * HD_];
__device__ float g_v[B_ * H_ * L_ * HD_];
__device__ float g_ao[M_ * C_];              // attention output, [b*L + l][h*128 + d]

// ---------------------------------------------------------------------------
// Kernel 1: QKV GEMM  qkv[m,n] = sum_k x[m,k] * W_qkv[n,k] + bias[n]
// 128x128 tile, BK=16, 256 threads, 8x8 per thread.
// Epilogue scatters into g_q / g_k / g_v with [b,h,l,d] layout.
// ---------------------------------------------------------------------------
__global__ void __launch_bounds__(256, 2)
qkv_gemm(const float* __restrict__ X, const float* __restrict__ W,
         const float* __restrict__ qb, const float* __restrict__ vb)
{
    __shared__ float As[16][128];
    __shared__ float Bs[16][128];

    const int n0 = blockIdx.x * 128;
    const int m0 = blockIdx.y * 128;
    const int tid = threadIdx.x;
    const int tx = tid & 15;
    const int ty = tid >> 4;
    const int lr = tid >> 2;          // 0..63
    const int lc = (tid & 3) << 2;    // 0,4,8,12

    float acc[8][8];
#pragma unroll
    for (int i = 0; i < 8; i++)
#pragma unroll
        for (int j = 0; j < 8; j++) acc[i][j] = 0.f;

    for (int kt = 0; kt < K_; kt += 16) {
        // global loads into regs first
        float4 a0 = make_float4(0.f, 0.f, 0.f, 0.f);
        float4 a1 = make_float4(0.f, 0.f, 0.f, 0.f);
        const int gm0 = m0 + lr, gm1 = m0 + lr + 64;
        if (gm0 < M_) a0 = *(const float4*)(X + (size_t)gm0 * K_ + kt + lc);
        if (gm1 < M_) a1 = *(const float4*)(X + (size_t)gm1 * K_ + kt + lc);
        float4 b0 = *(const float4*)(W + (size_t)(n0 + lr) * K_ + kt + lc);
        float4 b1 = *(const float4*)(W + (size_t)(n0 + lr + 64) * K_ + kt + lc);

        __syncthreads();
        As[lc + 0][lr] = a0.x; As[lc + 1][lr] = a0.y; As[lc + 2][lr] = a0.z; As[lc + 3][lr] = a0.w;
        As[lc + 0][lr + 64] = a1.x; As[lc + 1][lr + 64] = a1.y; As[lc + 2][lr + 64] = a1.z; As[lc + 3][lr + 64] = a1.w;
        Bs[lc + 0][lr] = b0.x; Bs[lc + 1][lr] = b0.y; Bs[lc + 2][lr] = b0.z; Bs[lc + 3][lr] = b0.w;
        Bs[lc + 0][lr + 64] = b1.x; Bs[lc + 1][lr + 64] = b1.y; Bs[lc + 2][lr + 64] = b1.z; Bs[lc + 3][lr + 64] = b1.w;
        __syncthreads();

#pragma unroll
        for (int kk = 0; kk < 16; kk++) {
            float a_[8], b_[8];
            {
                float4 t0 = *(const float4*)&As[kk][ty * 8];
                float4 t1 = *(const float4*)&As[kk][ty * 8 + 4];
                a_[0] = t0.x; a_[1] = t0.y; a_[2] = t0.z; a_[3] = t0.w;
                a_[4] = t1.x; a_[5] = t1.y; a_[6] = t1.z; a_[7] = t1.w;
            }
            {
                float4 t0 = *(const float4*)&Bs[kk][tx * 8];
                float4 t1 = *(const float4*)&Bs[kk][tx * 8 + 4];
                b_[0] = t0.x; b_[1] = t0.y; b_[2] = t0.z; b_[3] = t0.w;
                b_[4] = t1.x; b_[5] = t1.y; b_[6] = t1.z; b_[7] = t1.w;
            }
#pragma unroll
            for (int i = 0; i < 8; i++)
#pragma unroll
                for (int j = 0; j < 8; j++) acc[i][j] += a_[i] * b_[j];
        }
    }

    // epilogue: tile spans exactly one (t, head) pair since 128 | n0
    const int t = n0 >> 11;               // 0=q, 1=k, 2=v
    const int h = (n0 & 2047) >> 7;
    float* dst = (t == 0) ? g_q : ((t == 1) ? g_k : g_v);
    const int dbase = tx * 8;

    float bias[8];
#pragma unroll
    for (int j = 0; j < 8; j++) {
        int d = dbase + j;
        bias[j] = (t == 0) ? qb[h * HD_ + d] : ((t == 2) ? vb[h * HD_ + d] : 0.f);
    }

#pragma unroll
    for (int i = 0; i < 8; i++) {
        int gm = m0 + ty * 8 + i;
        if (gm >= M_) continue;
        int b = gm / L_;
        int l = gm - b * L_;
        float* p = dst + ((size_t)(b * H_ + h) * L_ + l) * HD_ + dbase;
        float4 o0, o1;
        o0.x = acc[i][0] + bias[0]; o0.y = acc[i][1] + bias[1];
        o0.z = acc[i][2] + bias[2]; o0.w = acc[i][3] + bias[3];
        o1.x = acc[i][4] + bias[4]; o1.y = acc[i][5] + bias[5];
        o1.z = acc[i][6] + bias[6]; o1.w = acc[i][7] + bias[7];
        *(float4*)p = o0;
        *(float4*)(p + 4) = o1;
    }
}

// ---------------------------------------------------------------------------
// Kernel 2: L2-normalize q (×scale_mul) and k, then 2D RoPE on both.
// One warp per (bh, l) row; lane owns dims [4*lane, 4*lane+4) = rope pairs 2*lane, 2*lane+1.
// ---------------------------------------------------------------------------
__global__ void __launch_bounds__(256)
norm_rope(const float* __restrict__ sml, const float* __restrict__ rope)
{
    const int gw = blockIdx.x * 8 + (threadIdx.x >> 5);
    const int lane = threadIdx.x & 31;
    if (gw >= B_ * H_ * L_) return;
    const int l = gw % L_;
    const int h = (gw / L_) % H_;

    float2 cc = *(const float2*)(rope + (size_t)l * 64 + lane * 2);
    float2 ss = *(const float2*)(rope + (size_t)L_ * 64 + (size_t)l * 64 + lane * 2);
    const float scale = __expf(fminf(sml[h], 4.605170185988091f));  // log(100)
    const size_t base = (size_t)gw * HD_ + lane * 4;

    // q
    {
        float4 v = *(const float4*)(g_q + base);
        float ssq = v.x * v.x + v.y * v.y + v.z * v.z + v.w * v.w;
#pragma unroll
        for (int o = 16; o; o >>= 1) ssq += __shfl_xor_sync(0xffffffffu, ssq, o);
        float inv = scale / fmaxf(sqrtf(ssq), 1e-12f);
        v.x *= inv; v.y *= inv; v.z *= inv; v.w *= inv;
        float4 r;
        r.x = cc.x * v.x - ss.x * v.y;
        r.y = ss.x * v.x + cc.x * v.y;
        r.z = cc.y * v.z - ss.y * v.w;
        r.w = ss.y * v.z + cc.y * v.w;
        *(float4*)(g_q + base) = r;
    }
    // k
    {
        float4 v = *(const float4*)(g_k + base);
        float ssq = v.x * v.x + v.y * v.y + v.z * v.z + v.w * v.w;
#pragma unroll
        for (int o = 16; o; o >>= 1) ssq += __shfl_xor_sync(0xffffffffu, ssq, o);
        float inv = 1.f / fmaxf(sqrtf(ssq), 1e-12f);
        v.x *= inv; v.y *= inv; v.z *= inv; v.w *= inv;
        float4 r;
        r.x = cc.x * v.x - ss.x * v.y;
        r.y = ss.x * v.x + cc.x * v.y;
        r.z = cc.y * v.z - ss.y * v.w;
        r.w = ss.y * v.z + cc.y * v.w;
        *(float4*)(g_k + base) = r;
    }
}

// ---------------------------------------------------------------------------
// Kernel 3: block-causal flash attention (fp32, online softmax).
// Q tile = 128 queries, KV tile = 64 keys, 256 threads (16x16):
//   S phase : thread (ty,tx) computes rows ty*8..+7, cols tx*4..+3
//   PV phase: same rows, cols tx*8..+7, O accumulated in registers.
// m/l/alpha stay in registers (same row ownership in both phases).
// ---------------------------------------------------------------------------
#define QT 128
#define KT 64
#define QP 130   // Qs pitch: conflict-free half-warp broadcasts
#define PP 66    // Ps pitch: conflict-free half-warp broadcasts

__global__ void __launch_bounds__(256, 1)
flash_attn()
{
    extern __shared__ float smf[];
    float* Qs  = smf;                  // [QT][QP]
    float* Kst = Qs + QT * QP;         // [128 d][KT]  (transposed K tile)
    float* Vs  = Kst + 128 * KT;       // [KT][128]
    float* Ps  = Vs + KT * 128;        // [QT][PP]

    const int bh = blockIdx.y;
    const int q0 = (gridDim.x - 1 - blockIdx.x) * QT;   // heavy tiles launch first
    const float* qp = g_q + (size_t)bh * L_ * HD_;
    const float* kp = g_k + (size_t)bh * L_ * HD_;
    const float* vp = g_v + (size_t)bh * L_ * HD_;
    const int tid = threadIdx.x;
    const int tx = tid & 15;
    const int ty = tid >> 4;

    // load Q tile (rows beyond L zeroed)
    for (int idx = tid; idx < QT * 32; idx += 256) {
        int r = idx >> 5;
        int c4 = (idx & 31) << 2;
        float4 v = make_float4(0.f, 0.f, 0.f, 0.f);
        if (q0 + r < L_) v = *(const float4*)(qp + (size_t)(q0 + r) * HD_ + c4);
        Qs[r * QP + c4 + 0] = v.x;
        Qs[r * QP + c4 + 1] = v.y;
        Qs[r * QP + c4 + 2] = v.z;
        Qs[r * QP + c4 + 3] = v.w;
    }

    // per-row visible kv length
    int kendr[8];
#pragma unroll
    for (int i = 0; i < 8; i++) {
        int lq = q0 + ty * 8 + i;
        int ke = 0;
        if (lq < L_) {
            ke = 2521;
#pragma unroll
            for (int tt = 0; tt < 10; tt++) {
                if (lq < d_cum[tt]) { ke = d_cum[tt]; break; }
            }
        }
        kendr[i] = ke;
    }
    int lql = min(q0 + QT - 1, L_ - 1);
    int kmax = 2521;
#pragma unroll
    for (int tt = 0; tt < 10; tt++) {
        if (lql < d_cum[tt]) { kmax = d_cum[tt]; break; }
    }

    float m_i[8], l_i[8], O[8][8];
#pragma unroll
    for (int i = 0; i < 8; i++) {
        m_i[i] = -1e30f;
        l_i[i] = 0.f;
#pragma unroll
        for (int j = 0; j < 8; j++) O[i][j] = 0.f;
    }

    const int lr = tid >> 2;          // 0..63 key row for loads
    const int cb = (tid & 3) << 2;    // 0,4,8,12

    for (int k0 = 0; k0 < kmax; k0 += KT) {
        __syncthreads();   // prev phase done with Kst/Vs/Ps (also publishes Qs on iter 0)

        // load K (transposed) and V tiles
        {
            const bool ok = (k0 + lr) < L_;
            const float* krow = kp + (size_t)(k0 + lr) * HD_;
            const float* vrow = vp + (size_t)(k0 + lr) * HD_;
#pragma unroll
            for (int i2 = 0; i2 < 8; i2++) {
                int c = cb + i2 * 16;
                float4 kv = ok ? *(const float4*)(krow + c) : make_float4(0.f, 0.f, 0.f, 0.f);
                Kst[(c + 0) * KT + lr] = kv.x;
                Kst[(c + 1) * KT + lr] = kv.y;
                Kst[(c + 2) * KT + lr] = kv.z;
                Kst[(c + 3) * KT + lr] = kv.w;
                float4 vv = ok ? *(const float4*)(vrow + c) : make_float4(0.f, 0.f, 0.f, 0.f);
                *(float4*)&Vs[lr * 128 + c] = vv;
            }
        }
        __syncthreads();

        // S = Q Kᵀ  (8x4 per thread)
        float s[8][4];
#pragma unroll
        for (int i = 0; i < 8; i++)
#pragma unroll
            for (int j = 0; j < 4; j++) s[i][j] = 0.f;

        for (int d = 0; d < 128; d++) {
            float4 kf = *(const float4*)&Kst[d * KT + tx * 4];
#pragma unroll
            for (int i = 0; i < 8; i++) {
                float qv = Qs[(ty * 8 + i) * QP + d];
                s[i][0] += qv * kf.x;
                s[i][1] += qv * kf.y;
                s[i][2] += qv * kf.z;
                s[i][3] += qv * kf.w;
            }
        }

        // mask + online softmax (rows owned by 16-lane half-warp groups)
        float alpha_r[8];
#pragma unroll
        for (int i = 0; i < 8; i++) {
            float rmax = -1e30f;
#pragma unroll
            for (int j = 0; j < 4; j++) {
                if (k0 + tx * 4 + j >= kendr[i]) s[i][j] = -1e30f;
                rmax = fmaxf(rmax, s[i][j]);
            }
#pragma unroll
            for (int o = 8; o; o >>= 1)
                rmax = fmaxf(rmax, __shfl_xor_sync(0xffffffffu, rmax, o, 16));
            float mn = fmaxf(m_i[i], rmax);
            float al = __expf(m_i[i] - mn);    // (-1e30)-(-1e30)=0 → 1; keeps O/l consistent
            float rs = 0.f;
#pragma unroll
            for (int j = 0; j < 4; j++) {
                float pv = (s[i][j] > -5e29f) ? __expf(s[i][j] - mn) : 0.f;
                s[i][j] = pv;
                rs += pv;
            }
#pragma unroll
            for (int o = 8; o; o >>= 1)
                rs += __shfl_xor_sync(0xffffffffu, rs, o, 16);
            l_i[i] = l_i[i] * al + rs;
            m_i[i] = mn;
            alpha_r[i] = al;
            Ps[(ty * 8 + i) * PP + tx * 4 + 0] = s[i][0];
            Ps[(ty * 8 + i) * PP + tx * 4 + 1] = s[i][1];
            Ps[(ty * 8 + i) * PP + tx * 4 + 2] = s[i][2];
            Ps[(ty * 8 + i) * PP + tx * 4 + 3] = s[i][3];
        }
        __syncthreads();

        // O = O*alpha + P V   (8x8 per thread)
#pragma unroll
        for (int i = 0; i < 8; i++) {
            float al = alpha_r[i];
#pragma unroll
            for (int j = 0; j < 8; j++) O[i][j] *= al;
        }
        for (int kk = 0; kk < KT; kk++) {
            float4 v0 = *(const float4*)&Vs[kk * 128 + tx * 8];
            float4 v1 = *(const float4*)&Vs[kk * 128 + tx * 8 + 4];
#pragma unroll
            for (int i = 0; i < 8; i++) {
                float pv = Ps[(ty * 8 + i) * PP + kk];
                O[i][0] += pv * v0.x; O[i][1] += pv * v0.y;
                O[i][2] += pv * v0.z; O[i][3] += pv * v0.w;
                O[i][4] += pv * v1.x; O[i][5] += pv * v1.y;
                O[i][6] += pv * v1.z; O[i][7] += pv * v1.w;
            }
        }
    }

    // epilogue: normalize by l, write [b, l, h*128 + d]
    const int b = bh >> 4;
    const int h = bh & 15;
#pragma unroll
    for (int i = 0; i < 8; i++) {
        int lq = q0 + ty * 8 + i;
        if (lq >= L_) continue;
        float inv = 1.f / l_i[i];
        float* dp = g_ao + ((size_t)(b * L_ + lq) * C_) + h * HD_ + tx * 8;
        float4 o0, o1;
        o0.x = O[i][0] * inv; o0.y = O[i][1] * inv; o0.z = O[i][2] * inv; o0.w = O[i][3] * inv;
        o1.x = O[i][4] * inv; o1.y = O[i][5] * inv; o1.z = O[i][6] * inv; o1.w = O[i][7] * inv;
        *(float4*)dp = o0;
        *(float4*)(dp + 4) = o1;
    }
}

// ---------------------------------------------------------------------------
// Kernel 4: projection GEMM  out[m,n] = sum_k g_ao[m,k] * proj_W[n,k] + proj_b[n]
// ---------------------------------------------------------------------------
__global__ void __launch_bounds__(256, 2)
proj_gemm(const float* __restrict__ W, const float* __restrict__ pb, float* __restrict__ out)
{
    __shared__ float As[16][128];
    __shared__ float Bs[16][128];

    const int n0 = blockIdx.x * 128;
    const int m0 = blockIdx.y * 128;
    const int tid = threadIdx.x;
    const int tx = tid & 15;
    const int ty = tid >> 4;
    const int lr = tid >> 2;
    const int lc = (tid & 3) << 2;

    float acc[8][8];
#pragma unroll
    for (int i = 0; i < 8; i++)
#pragma unroll
        for (int j = 0; j < 8; j++) acc[i][j] = 0.f;

    for (int kt = 0; kt < C_; kt += 16) {
        float4 a0 = make_float4(0.f, 0.f, 0.f, 0.f);
        float4 a1 = make_float4(0.f, 0.f, 0.f, 0.f);
        const int gm0 = m0 + lr, gm1 = m0 + lr + 64;
        if (gm0 < M_) a0 = *(const float4*)(g_ao + (size_t)gm0 * C_ + kt + lc);
        if (gm1 < M_) a1 = *(const float4*)(g_ao + (size_t)gm1 * C_ + kt + lc);
        float4 b0 = *(const float4*)(W + (size_t)(n0 + lr) * C_ + kt + lc);
        float4 b1 = *(const float4*)(W + (size_t)(n0 + lr + 64) * C_ + kt + lc);

        __syncthreads();
        As[lc + 0][lr] = a0.x; As[lc + 1][lr] = a0.y; As[lc + 2][lr] = a0.z; As[lc + 3][lr] = a0.w;
        As[lc + 0][lr + 64] = a1.x; As[lc + 1][lr + 64] = a1.y; As[lc + 2][lr + 64] = a1.z; As[lc + 3][lr + 64] = a1.w;
        Bs[lc + 0][lr] = b0.x; Bs[lc + 1][lr] = b0.y; Bs[lc + 2][lr] = b0.z; Bs[lc + 3][lr] = b0.w;
        Bs[lc + 0][lr + 64] = b1.x; Bs[lc + 1][lr + 64] = b1.y; Bs[lc + 2][lr + 64] = b1.z; Bs[lc + 3][lr + 64] = b1.w;
        __syncthreads();

#pragma unroll
        for (int kk = 0; kk < 16; kk++) {
            float a_[8], b_[8];
            {
                float4 t0 = *(const float4*)&As[kk][ty * 8];
                float4 t1 = *(const float4*)&As[kk][ty * 8 + 4];
                a_[0] = t0.x; a_[1] = t0.y; a_[2] = t0.z; a_[3] = t0.w;
                a_[4] = t1.x; a_[5] = t1.y; a_[6] = t1.z; a_[7] = t1.w;
            }
            {
                float4 t0 = *(const float4*)&Bs[kk][tx * 8];
                float4 t1 = *(const float4*)&Bs[kk][tx * 8 + 4];
                b_[0] = t0.x; b_[1] = t0.y; b_[2] = t0.z; b_[3] = t0.w;
                b_[4] = t1.x; b_[5] = t1.y; b_[6] = t1.z; b_[7] = t1.w;
            }
#pragma unroll
            for (int i = 0; i < 8; i++)
#pragma unroll
                for (int j = 0; j < 8; j++) acc[i][j] += a_[i] * b_[j];
        }
    }

    float bias[8];
#pragma unroll
    for (int j = 0; j < 8; j++) bias[j] = pb[n0 + tx * 8 + j];

#pragma unroll
    for (int i = 0; i < 8; i++) {
        int gm = m0 + ty * 8 + i;
        if (gm >= M_) continue;
        float* p = out + (size_t)gm * C_ + n0 + tx * 8;
        float4 o0, o1;
        o0.x = acc[i][0] + bias[0]; o0.y = acc[i][1] + bias[1];
        o0.z = acc[i][2] + bias[2]; o0.w = acc[i][3] + bias[3];
        o1.x = acc[i][4] + bias[4]; o1.y = acc[i][5] + bias[5];
        o1.z = acc[i][6] + bias[6]; o1.w = acc[i][7] + bias[7];
        *(float4*)p = o0;
        *(float4*)(p + 4) = o1;
    }
}

// ---------------------------------------------------------------------------
// launch
// ---------------------------------------------------------------------------
extern "C" void kernel_launch(void* const* d_in, const int* in_sizes, int n_in,
                              void* d_out, int out_size)
{
    const float* x    = (const float*)d_in[0];
    const float* Wqkv = (const float*)d_in[1];
    const float* qb   = (const float*)d_in[2];
    const float* vb   = (const float*)d_in[3];
    const float* sml  = (const float*)d_in[4];
    const float* pW   = (const float*)d_in[5];
    const float* pb   = (const float*)d_in[6];
    const float* rope = (const float*)d_in[7];
    // d_in[8] = attn_bias: mask computed analytically from d_cum, not read.
    float* out = (float*)d_out;

    dim3 g1(NQKV / 128, (M_ + 127) / 128);   // 48 x 40
    qkv_gemm<<<g1, 256>>>(x, Wqkv, qb, vb);

    int nwarps = B_ * H_ * L_;               // 80672
    norm_rope<<<(nwarps + 7) / 8, 256>>>(sml, rope);

    size_t shm = (size_t)(QT * QP + 128 * KT + KT * 128 + QT * PP) * sizeof(float); // 165,888 B
    cudaFuncSetAttribute(flash_attn, cudaFuncAttributeMaxDynamicSharedMemorySize, (int)shm);
    dim3 g3((L_ + QT - 1) / QT, B_ * H_);    // 20 x 32
    flash_attn<<<g3, 256, shm>>>();

    dim3 g4(C_ / 128, (M_ + 127) / 128);     // 16 x 40
    proj_gemm<<<g4, 256>>>(pW, pb, out);
}

// round 3
// speedup vs baseline: 1.2441x; 1.2441x over previous
#include <cuda_runtime.h>
#include <cuda_bf16.h>
#include <cstdint>
#include <math.h>

// ---------------------------------------------------------------------------
// Problem constants
// ---------------------------------------------------------------------------
#define B_   2
#define L_   2521
#define C_   2048
#define H_   16
#define HD_  128
#define M_   (B_ * L_)          // 5042
#define K_   2048
#define NQKV 6144

__device__ __constant__ int d_cum[10] = {1, 5, 21, 57, 121, 265, 521, 921, 1497, 2521};

// scratch
__device__ float g_q[B_ * H_ * L_ * HD_];
__device__ float g_k[B_ * H_ * L_ * HD_];
__device__ float g_v[B_ * H_ * L_ * HD_];
__device__ float g_ao[M_ * C_];

// ---------------------------------------------------------------------------
// helpers: tf32 convert + mma.m16n8k8
// ---------------------------------------------------------------------------
__device__ __forceinline__ uint32_t f2tf(float x) {
    uint32_t r;
    asm("cvt.rna.tf32.f32 %0, %1;" : "=r"(r) : "f"(x));
    return r;
}
__device__ __forceinline__ float tf32r(float x) { return __uint_as_float(f2tf(x)); }

__device__ __forceinline__ void mma8(float* c,
                                     uint32_t a0, uint32_t a1, uint32_t a2, uint32_t a3,
                                     uint32_t b0, uint32_t b1)
{
    asm volatile(
        "mma.sync.aligned.m16n8k8.row.col.f32.tf32.tf32.f32 "
        "{%0,%1,%2,%3}, {%4,%5,%6,%7}, {%8,%9}, {%0,%1,%2,%3};"
        : "+f"(c[0]), "+f"(c[1]), "+f"(c[2]), "+f"(c[3])
        : "r"(a0), "r"(a1), "r"(a2), "r"(a3), "r"(b0), "r"(b1));
}

// ---------------------------------------------------------------------------
// Shared GEMM core: C[128x128] = A[128xK] * B[128xK]^T, 3xTF32, BK=32.
// 256 threads = 8 warps (4m x 2n), warp tile 32x64 (2 m-tiles x 8 n-tiles).
// acc[mi][j][4] per thread. Smem pitch 36 (== 4 mod 32) -> conflict-free frags.
// ---------------------------------------------------------------------------
#define GP 36

__device__ __forceinline__ void gemm_core_3xtf32(
    const float* __restrict__ A, const float* __restrict__ Bm,
    int m0, int n0, float* sm, float acc[2][8][4], int tid)
{
    float* Ah = sm;
    float* Al = Ah + 128 * GP;
    float* Bh = Al + 128 * GP;
    float* Bl = Bh + 128 * GP;

    const int lane = tid & 31, wid = tid >> 5;
    const int g = lane >> 2, t = lane & 3;
    const int mw = (wid >> 1) * 32, nw = (wid & 1) * 64;
    const int row = tid & 127, half = (tid >> 7) * 16;

    const float* ag = A + (size_t)(m0 + row) * K_ + half;
    const float* bg = Bm + (size_t)(n0 + row) * K_ + half;
    const bool aok = (m0 + row) < M_;

    float4 pa[4], pb[4];
#pragma unroll
    for (int i = 0; i < 4; i++) {
        pa[i] = aok ? *(const float4*)(ag + 4 * i) : make_float4(0.f, 0.f, 0.f, 0.f);
        pb[i] = *(const float4*)(bg + 4 * i);
    }

    for (int kt = 0; kt < K_; kt += 32) {
        __syncthreads();
#pragma unroll
        for (int i = 0; i < 4; i++) {
            float4 h, l;
            h.x = tf32r(pa[i].x); l.x = tf32r(pa[i].x - h.x);
            h.y = tf32r(pa[i].y); l.y = tf32r(pa[i].y - h.y);
            h.z = tf32r(pa[i].z); l.z = tf32r(pa[i].z - h.z);
            h.w = tf32r(pa[i].w); l.w = tf32r(pa[i].w - h.w);
            *(float4*)(Ah + row * GP + half + 4 * i) = h;
            *(float4*)(Al + row * GP + half + 4 * i) = l;
            h.x = tf32r(pb[i].x); l.x = tf32r(pb[i].x - h.x);
            h.y = tf32r(pb[i].y); l.y = tf32r(pb[i].y - h.y);
            h.z = tf32r(pb[i].z); l.z = tf32r(pb[i].z - h.z);
            h.w = tf32r(pb[i].w); l.w = tf32r(pb[i].w - h.w);
            *(float4*)(Bh + row * GP + half + 4 * i) = h;
            *(float4*)(Bl + row * GP + half + 4 * i) = l;
        }
        __syncthreads();

        if (kt + 32 < K_) {
#pragma unroll
            for (int i = 0; i < 4; i++) {
                pa[i] = aok ? *(const float4*)(ag + kt + 32 + 4 * i) : make_float4(0.f, 0.f, 0.f, 0.f);
                pb[i] = *(const float4*)(bg + kt + 32 + 4 * i);
            }
        }

#pragma unroll
        for (int kk = 0; kk < 32; kk += 8) {
            uint32_t ah[2][4], al[2][4];
#pragma unroll
            for (int mi = 0; mi < 2; mi++) {
                int r0 = mw + 16 * mi + g;
                ah[mi][0] = __float_as_uint(Ah[r0 * GP + kk + t]);
                ah[mi][1] = __float_as_uint(Ah[(r0 + 8) * GP + kk + t]);
                ah[mi][2] = __float_as_uint(Ah[r0 * GP + kk + t + 4]);
                ah[mi][3] = __float_as_uint(Ah[(r0 + 8) * GP + kk + t + 4]);
                al[mi][0] = __float_as_uint(Al[r0 * GP + kk + t]);
                al[mi][1] = __float_as_uint(Al[(r0 + 8) * GP + kk + t]);
                al[mi][2] = __float_as_uint(Al[r0 * GP + kk + t + 4]);
                al[mi][3] = __float_as_uint(Al[(r0 + 8) * GP + kk + t + 4]);
            }
#pragma unroll
            for (int j = 0; j < 8; j++) {
                int cn = nw + 8 * j + g;
                uint32_t bh0 = __float_as_uint(Bh[cn * GP + kk + t]);
                uint32_t bh1 = __float_as_uint(Bh[cn * GP + kk + t + 4]);
                uint32_t bl0 = __float_as_uint(Bl[cn * GP + kk + t]);
                uint32_t bl1 = __float_as_uint(Bl[cn * GP + kk + t + 4]);
#pragma unroll
                for (int mi = 0; mi < 2; mi++) {
                    mma8(acc[mi][j], ah[mi][0], ah[mi][1], ah[mi][2], ah[mi][3], bh0, bh1);
                    mma8(acc[mi][j], ah[mi][0], ah[mi][1], ah[mi][2], ah[mi][3], bl0, bl1);
                    mma8(acc[mi][j], al[mi][0], al[mi][1], al[mi][2], al[mi][3], bh0, bh1);
                }
            }
        }
    }
}

// ---------------------------------------------------------------------------
// Kernel 1: QKV GEMM + scatter epilogue
// ---------------------------------------------------------------------------
__global__ void __launch_bounds__(256, 1)
qkv_gemm(const float* __restrict__ X, const float* __restrict__ W,
         const float* __restrict__ qb, const float* __restrict__ vb)
{
    extern __shared__ float sm[];
    float acc[2][8][4];
#pragma unroll
    for (int a = 0; a < 2; a++)
#pragma unroll
        for (int b = 0; b < 8; b++)
#pragma unroll
            for (int c = 0; c < 4; c++) acc[a][b][c] = 0.f;

    const int n0 = blockIdx.x * 128;
    const int m0 = blockIdx.y * 128;
    gemm_core_3xtf32(X, W, m0, n0, sm, acc, threadIdx.x);

    const int lane = threadIdx.x & 31, wid = threadIdx.x >> 5;
    const int g = lane >> 2, t = lane & 3;
    const int mw = (wid >> 1) * 32, nw = (wid & 1) * 64;

    const int tq = n0 >> 11;                  // 0=q,1=k,2=v
    const int h = (n0 & 2047) >> 7;
    float* dst = (tq == 0) ? g_q : ((tq == 1) ? g_k : g_v);

    float2 bias[8];
#pragma unroll
    for (int j = 0; j < 8; j++) {
        int d = nw + 8 * j + 2 * t;
        float b0 = 0.f, b1 = 0.f;
        if (tq == 0) { b0 = qb[h * HD_ + d]; b1 = qb[h * HD_ + d + 1]; }
        else if (tq == 2) { b0 = vb[h * HD_ + d]; b1 = vb[h * HD_ + d + 1]; }
        bias[j] = make_float2(b0, b1);
    }

#pragma unroll
    for (int mi = 0; mi < 2; mi++)
#pragma unroll
        for (int rr = 0; rr < 2; rr++) {
            int gm = m0 + mw + 16 * mi + g + 8 * rr;
            if (gm >= M_) continue;
            int b = gm / L_;
            int l = gm - b * L_;
            float* p = dst + ((size_t)(b * H_ + h) * L_ + l) * HD_;
#pragma unroll
            for (int j = 0; j < 8; j++) {
                int d = nw + 8 * j + 2 * t;
                float2 o;
                o.x = acc[mi][j][2 * rr] + bias[j].x;
                o.y = acc[mi][j][2 * rr + 1] + bias[j].y;
                *(float2*)(p + d) = o;
            }
        }
}

// ---------------------------------------------------------------------------
// Kernel 2: norm + rope (fp32)
// ---------------------------------------------------------------------------
__global__ void __launch_bounds__(256)
norm_rope(const float* __restrict__ sml, const float* __restrict__ rope)
{
    const int gw = blockIdx.x * 8 + (threadIdx.x >> 5);
    const int lane = threadIdx.x & 31;
    if (gw >= B_ * H_ * L_) return;
    const int l = gw % L_;
    const int h = (gw / L_) % H_;

    float2 cc = *(const float2*)(rope + (size_t)l * 64 + lane * 2);
    float2 ss = *(const float2*)(rope + (size_t)L_ * 64 + (size_t)l * 64 + lane * 2);
    const float scale = __expf(fminf(sml[h], 4.605170185988091f));
    const size_t base = (size_t)gw * HD_ + lane * 4;

    {
        float4 v = *(const float4*)(g_q + base);
        float ssq = v.x * v.x + v.y * v.y + v.z * v.z + v.w * v.w;
#pragma unroll
        for (int o = 16; o; o >>= 1) ssq += __shfl_xor_sync(0xffffffffu, ssq, o);
        float inv = scale / fmaxf(sqrtf(ssq), 1e-12f);
        v.x *= inv; v.y *= inv; v.z *= inv; v.w *= inv;
        float4 r;
        r.x = cc.x * v.x - ss.x * v.y;
        r.y = ss.x * v.x + cc.x * v.y;
        r.z = cc.y * v.z - ss.y * v.w;
        r.w = ss.y * v.z + cc.y * v.w;
        *(float4*)(g_q + base) = r;
    }
    {
        float4 v = *(const float4*)(g_k + base);
        float ssq = v.x * v.x + v.y * v.y + v.z * v.z + v.w * v.w;
#pragma unroll
        for (int o = 16; o; o >>= 1) ssq += __shfl_xor_sync(0xffffffffu, ssq, o);
        float inv = 1.f / fmaxf(sqrtf(ssq), 1e-12f);
        v.x *= inv; v.y *= inv; v.z *= inv; v.w *= inv;
        float4 r;
        r.x = cc.x * v.x - ss.x * v.y;
        r.y = ss.x * v.x + cc.x * v.y;
        r.z = cc.y * v.z - ss.y * v.w;
        r.w = ss.y * v.z + cc.y * v.w;
        *(float4*)(g_k + base) = r;
    }
}

// ---------------------------------------------------------------------------
// Kernel 3: flash attention with tf32 mma.
// 128 q x 64 k tiles, 256 threads = 8 warps; warp owns 16 q-rows.
// ---------------------------------------------------------------------------
#define QTP 132
#define VTP 68

__device__ __forceinline__ int kend_of(int lq) {
    if (lq >= L_) return 0;
    int ke = 2521;
#pragma unroll
    for (int i = 9; i >= 0; i--)
        if (lq < d_cum[i]) ke = d_cum[i];
    return ke;
}

__global__ void __launch_bounds__(256, 1)
flash_attn()
{
    extern __shared__ float sm[];
    float* Qs  = sm;                       // [128][132]
    float* Ks  = Qs + 128 * QTP;           // [64][132]
    float* Vst = Ks + 64 * QTP;            // [128][68]  V transposed [d][key]
    float* Ps  = Vst + 128 * VTP;          // [128][68]

    const int bh = blockIdx.y;
    const int q0 = (gridDim.x - 1 - blockIdx.x) * 128;
    const float* qp = g_q + (size_t)bh * L_ * HD_;
    const float* kp = g_k + (size_t)bh * L_ * HD_;
    const float* vp = g_v + (size_t)bh * L_ * HD_;
    const int tid = threadIdx.x, lane = tid & 31, wid = tid >> 5;
    const int g = lane >> 2, t = lane & 3;

    // Q tile load (tf32-rounded)
    {
        int r = tid >> 1, h64 = (tid & 1) * 64;
        const float* src = qp + (size_t)(q0 + r) * HD_ + h64;
        bool ok = (q0 + r) < L_;
#pragma unroll
        for (int i = 0; i < 16; i++) {
            float4 v = ok ? *(const float4*)(src + 4 * i) : make_float4(0.f, 0.f, 0.f, 0.f);
            float4 c;
            c.x = tf32r(v.x); c.y = tf32r(v.y); c.z = tf32r(v.z); c.w = tf32r(v.w);
            *(float4*)(Qs + r * QTP + h64 + 4 * i) = c;
        }
    }

    const int rowbase = wid * 16 + g;
    const int kend0 = kend_of(q0 + rowbase);
    const int kend1 = kend_of(q0 + rowbase + 8);
    int kmax;
    {
        int lql = min(q0 + 127, L_ - 1);
        kmax = 2521;
#pragma unroll
        for (int i = 9; i >= 0; i--)
            if (lql < d_cum[i]) kmax = d_cum[i];
    }

    float m0v = -1e30f, m1v = -1e30f, l0v = 0.f, l1v = 0.f;
    float O[16][4];
#pragma unroll
    for (int j = 0; j < 16; j++)
#pragma unroll
        for (int c = 0; c < 4; c++) O[j][c] = 0.f;

    for (int k0 = 0; k0 < kmax; k0 += 64) {
        __syncthreads();   // prior PV done with Ks/Vst/Ps (and publishes Qs on iter 0)

        // K tile: [64 keys][128 d]
        {
            int krow = tid >> 2, seg = (tid & 3) * 32;
            bool ok = (k0 + krow) < L_;
            const float* src = kp + (size_t)(k0 + krow) * HD_ + seg;
#pragma unroll
            for (int i = 0; i < 8; i++) {
                float4 v = ok ? *(const float4*)(src + 4 * i) : make_float4(0.f, 0.f, 0.f, 0.f);
                float4 c;
                c.x = tf32r(v.x); c.y = tf32r(v.y); c.z = tf32r(v.z); c.w = tf32r(v.w);
                *(float4*)(Ks + krow * QTP + seg + 4 * i) = c;
            }
        }
        // V tile transposed: Vst[d][key]
        {
            int vkey = tid & 63, vseg = (tid >> 6) * 32;
            bool ok = (k0 + vkey) < L_;
            const float* src = vp + (size_t)(k0 + vkey) * HD_ + vseg;
#pragma unroll
            for (int i = 0; i < 8; i++) {
                float4 v = ok ? *(const float4*)(src + 4 * i) : make_float4(0.f, 0.f, 0.f, 0.f);
                int c = vseg + 4 * i;
                Vst[(c + 0) * VTP + vkey] = tf32r(v.x);
                Vst[(c + 1) * VTP + vkey] = tf32r(v.y);
                Vst[(c + 2) * VTP + vkey] = tf32r(v.z);
                Vst[(c + 3) * VTP + vkey] = tf32r(v.w);
            }
        }
        __syncthreads();

        // S = Q K^T
        float sc[8][4];
#pragma unroll
        for (int j = 0; j < 8; j++)
#pragma unroll
            for (int c = 0; c < 4; c++) sc[j][c] = 0.f;

#pragma unroll
        for (int kk = 0; kk < 128; kk += 8) {
            uint32_t a0 = __float_as_uint(Qs[rowbase * QTP + kk + t]);
            uint32_t a1 = __float_as_uint(Qs[(rowbase + 8) * QTP + kk + t]);
            uint32_t a2 = __float_as_uint(Qs[rowbase * QTP + kk + t + 4]);
            uint32_t a3 = __float_as_uint(Qs[(rowbase + 8) * QTP + kk + t + 4]);
#pragma unroll
            for (int j = 0; j < 8; j++) {
                uint32_t b0 = __float_as_uint(Ks[(8 * j + g) * QTP + kk + t]);
                uint32_t b1 = __float_as_uint(Ks[(8 * j + g) * QTP + kk + t + 4]);
                mma8(sc[j], a0, a1, a2, a3, b0, b1);
            }
        }

        // mask + online softmax (rows: rowbase, rowbase+8)
        float rmax0 = -1e30f, rmax1 = -1e30f;
#pragma unroll
        for (int j = 0; j < 8; j++) {
            int c0 = k0 + 8 * j + 2 * t, c1 = c0 + 1;
            if (c0 >= kend0) sc[j][0] = -1e30f;
            if (c1 >= kend0) sc[j][1] = -1e30f;
            if (c0 >= kend1) sc[j][2] = -1e30f;
            if (c1 >= kend1) sc[j][3] = -1e30f;
            rmax0 = fmaxf(rmax0, fmaxf(sc[j][0], sc[j][1]));
            rmax1 = fmaxf(rmax1, fmaxf(sc[j][2], sc[j][3]));
        }
        rmax0 = fmaxf(rmax0, __shfl_xor_sync(0xffffffffu, rmax0, 1));
        rmax0 = fmaxf(rmax0, __shfl_xor_sync(0xffffffffu, rmax0, 2));
        rmax1 = fmaxf(rmax1, __shfl_xor_sync(0xffffffffu, rmax1, 1));
        rmax1 = fmaxf(rmax1, __shfl_xor_sync(0xffffffffu, rmax1, 2));

        float mn0 = fmaxf(m0v, rmax0), mn1 = fmaxf(m1v, rmax1);
        float al0 = __expf(m0v - mn0), al1 = __expf(m1v - mn1);
        float rs0 = 0.f, rs1 = 0.f;
#pragma unroll
        for (int j = 0; j < 8; j++) {
            float p0 = (sc[j][0] > -5e29f) ? __expf(sc[j][0] - mn0) : 0.f;
            float p1 = (sc[j][1] > -5e29f) ? __expf(sc[j][1] - mn0) : 0.f;
            float p2 = (sc[j][2] > -5e29f) ? __expf(sc[j][2] - mn1) : 0.f;
            float p3 = (sc[j][3] > -5e29f) ? __expf(sc[j][3] - mn1) : 0.f;
            rs0 += p0 + p1;
            rs1 += p2 + p3;
            int col = 8 * j + 2 * t;
            *(float2*)(Ps + rowbase * VTP + col) = make_float2(tf32r(p0), tf32r(p1));
            *(float2*)(Ps + (rowbase + 8) * VTP + col) = make_float2(tf32r(p2), tf32r(p3));
        }
        rs0 += __shfl_xor_sync(0xffffffffu, rs0, 1);
        rs0 += __shfl_xor_sync(0xffffffffu, rs0, 2);
        rs1 += __shfl_xor_sync(0xffffffffu, rs1, 1);
        rs1 += __shfl_xor_sync(0xffffffffu, rs1, 2);
        l0v = l0v * al0 + rs0;
        l1v = l1v * al1 + rs1;
        m0v = mn0; m1v = mn1;

#pragma unroll
        for (int j = 0; j < 16; j++) {
            O[j][0] *= al0; O[j][1] *= al0;
            O[j][2] *= al1; O[j][3] *= al1;
        }
        __syncthreads();   // Ps visible to all warps

        // O += P V
#pragma unroll
        for (int kk = 0; kk < 64; kk += 8) {
            uint32_t a0 = __float_as_uint(Ps[rowbase * VTP + kk + t]);
            uint32_t a1 = __float_as_uint(Ps[(rowbase + 8) * VTP + kk + t]);
            uint32_t a2 = __float_as_uint(Ps[rowbase * VTP + kk + t + 4]);
            uint32_t a3 = __float_as_uint(Ps[(rowbase + 8) * VTP + kk + t + 4]);
#pragma unroll
            for (int j = 0; j < 16; j++) {
                uint32_t b0 = __float_as_uint(Vst[(8 * j + g) * VTP + kk + t]);
                uint32_t b1 = __float_as_uint(Vst[(8 * j + g) * VTP + kk + t + 4]);
                mma8(O[j], a0, a1, a2, a3, b0, b1);
            }
        }
    }

    // epilogue
    const int b = bh >> 4;
    const int h = bh & 15;
#pragma unroll
    for (int rr = 0; rr < 2; rr++) {
        int lq = q0 + rowbase + 8 * rr;
        if (lq >= L_) continue;
        float inv = 1.f / (rr ? l1v : l0v);
        float* dp = g_ao + (size_t)(b * L_ + lq) * C_ + h * HD_;
#pragma unroll
        for (int j = 0; j < 16; j++) {
            float2 o;
            o.x = O[j][2 * rr] * inv;
            o.y = O[j][2 * rr + 1] * inv;
            *(float2*)(dp + 8 * j + 2 * t) = o;
        }
    }
}

// ---------------------------------------------------------------------------
// Kernel 4: projection GEMM
// ---------------------------------------------------------------------------
__global__ void __launch_bounds__(256, 1)
proj_gemm(const float* __restrict__ W, const float* __restrict__ pb, float* __restrict__ out)
{
    extern __shared__ float sm[];
    float acc[2][8][4];
#pragma unroll
    for (int a = 0; a < 2; a++)
#pragma unroll
        for (int b = 0; b < 8; b++)
#pragma unroll
            for (int c = 0; c < 4; c++) acc[a][b][c] = 0.f;

    const int n0 = blockIdx.x * 128;
    const int m0 = blockIdx.y * 128;
    gemm_core_3xtf32(g_ao, W, m0, n0, sm, acc, threadIdx.x);

    const int lane = threadIdx.x & 31, wid = threadIdx.x >> 5;
    const int g = lane >> 2, t = lane & 3;
    const int mw = (wid >> 1) * 32, nw = (wid & 1) * 64;

    float2 bias[8];
#pragma unroll
    for (int j = 0; j < 8; j++) {
        int n = n0 + nw + 8 * j + 2 * t;
        bias[j] = make_float2(pb[n], pb[n + 1]);
    }

#pragma unroll
    for (int mi = 0; mi < 2; mi++)
#pragma unroll
        for (int rr = 0; rr < 2; rr++) {
            int gm = m0 + mw + 16 * mi + g + 8 * rr;
            if (gm >= M_) continue;
            float* p = out + (size_t)gm * C_ + n0 + nw;
#pragma unroll
            for (int j = 0; j < 8; j++) {
                float2 o;
                o.x = acc[mi][j][2 * rr] + bias[j].x;
                o.y = acc[mi][j][2 * rr + 1] + bias[j].y;
                *(float2*)(p + 8 * j + 2 * t) = o;
            }
        }
}

// ---------------------------------------------------------------------------
// launch
// ---------------------------------------------------------------------------
extern "C" void kernel_launch(void* const* d_in, const int* in_sizes, int n_in,
                              void* d_out, int out_size)
{
    const float* x    = (const float*)d_in[0];
    const float* Wqkv = (const float*)d_in[1];
    const float* qb   = (const float*)d_in[2];
    const float* vb   = (const float*)d_in[3];
    const float* sml  = (const float*)d_in[4];
    const float* pW   = (const float*)d_in[5];
    const float* pb   = (const float*)d_in[6];
    const float* rope = (const float*)d_in[7];
    float* out = (float*)d_out;

    const size_t gemm_shm = (size_t)4 * 128 * GP * sizeof(float);   // 73,728 B
    const size_t flash_shm = (size_t)(128 * QTP + 64 * QTP + 128 * VTP + 128 * VTP) * sizeof(float); // 171,008 B

    cudaFuncSetAttribute(qkv_gemm, cudaFuncAttributeMaxDynamicSharedMemorySize, (int)gemm_shm);
    cudaFuncSetAttribute(proj_gemm, cudaFuncAttributeMaxDynamicSharedMemorySize, (int)gemm_shm);
    cudaFuncSetAttribute(flash_attn, cudaFuncAttributeMaxDynamicSharedMemorySize, (int)flash_shm);

    dim3 g1(NQKV / 128, (M_ + 127) / 128);   // 48 x 40
    qkv_gemm<<<g1, 256, gemm_shm>>>(x, Wqkv, qb, vb);

    int nwarps = B_ * H_ * L_;
    norm_rope<<<(nwarps + 7) / 8, 256>>>(sml, rope);

    dim3 g3((L_ + 127) / 128, B_ * H_);      // 20 x 32
    flash_attn<<<g3, 256, flash_shm>>>();

    dim3 g4(C_ / 128, (M_ + 127) / 128);     // 16 x 40
    proj_gemm<<<g4, 256, gemm_shm>>>(pW, pb, out);
}

// round 4
// speedup vs baseline: 1.9755x; 1.5879x over previous
#include <cuda_runtime.h>
#include <cuda_bf16.h>
#include <cstdint>
#include <math.h>

// ---------------------------------------------------------------------------
// Problem constants
// ---------------------------------------------------------------------------
#define B_   2
#define L_   2521
#define C_   2048
#define H_   16
#define HD_  128
#define M_   (B_ * L_)          // 5042
#define K_   2048
#define KP_  1024               // K/2 u32 pairs per row
#define NQKV 6144

__device__ __constant__ int d_cum[10] = {1, 5, 21, 57, 121, 265, 521, 921, 1497, 2521};

// f32 scratch
__device__ float g_q[B_ * H_ * L_ * HD_];
__device__ float g_k[B_ * H_ * L_ * HD_];
__device__ float g_v[B_ * H_ * L_ * HD_];

// split-bf16 scratch (u32 = packed bf16x2, pair-permuted layout)
__device__ uint32_t g_xh[M_ * KP_],   g_xl[M_ * KP_];      // x
__device__ uint32_t g_wh[NQKV * KP_], g_wl[NQKV * KP_];    // W_qkv
__device__ uint32_t g_pwh[C_ * KP_],  g_pwl[C_ * KP_];     // proj_W
__device__ uint32_t g_aoh[M_ * KP_],  g_aol[M_ * KP_];     // attention output

// ---------------------------------------------------------------------------
// helpers
// ---------------------------------------------------------------------------
__device__ __forceinline__ uint32_t f2tf(float x) {
    uint32_t r;
    asm("cvt.rna.tf32.f32 %0, %1;" : "=r"(r) : "f"(x));
    return r;
}
__device__ __forceinline__ float tf32r(float x) { return __uint_as_float(f2tf(x)); }

__device__ __forceinline__ void mma8(float* c,
                                     uint32_t a0, uint32_t a1, uint32_t a2, uint32_t a3,
                                     uint32_t b0, uint32_t b1)
{
    asm volatile(
        "mma.sync.aligned.m16n8k8.row.col.f32.tf32.tf32.f32 "
        "{%0,%1,%2,%3}, {%4,%5,%6,%7}, {%8,%9}, {%0,%1,%2,%3};"
        : "+f"(c[0]), "+f"(c[1]), "+f"(c[2]), "+f"(c[3])
        : "r"(a0), "r"(a1), "r"(a2), "r"(a3), "r"(b0), "r"(b1));
}

__device__ __forceinline__ void mma16(float* c,
                                      uint32_t a0, uint32_t a1, uint32_t a2, uint32_t a3,
                                      uint32_t b0, uint32_t b1)
{
    asm volatile(
        "mma.sync.aligned.m16n8k16.row.col.f32.bf16.bf16.f32 "
        "{%0,%1,%2,%3}, {%4,%5,%6,%7}, {%8,%9}, {%0,%1,%2,%3};"
        : "+f"(c[0]), "+f"(c[1]), "+f"(c[2]), "+f"(c[3])
        : "r"(a0), "r"(a1), "r"(a2), "r"(a3), "r"(b0), "r"(b1));
}

// permuted pair column: pair p (k = 2p, 2p+1) -> fragment-order column
__device__ __forceinline__ int pair_perm(int p) {
    int q = p & 15;
    return (p & ~15) + (q & 8) + (q & 3) * 2 + ((q >> 2) & 1);
}

__device__ __forceinline__ void split_pack(float x0, float x1, uint32_t& hp, uint32_t& lp) {
    __nv_bfloat16 h0 = __float2bfloat16_rn(x0);
    __nv_bfloat16 h1 = __float2bfloat16_rn(x1);
    float l0f = x0 - __bfloat162float(h0);
    float l1f = x1 - __bfloat162float(h1);
    __nv_bfloat16 l0 = __float2bfloat16_rn(l0f);
    __nv_bfloat16 l1 = __float2bfloat16_rn(l1f);
    hp = (uint32_t)__bfloat16_as_ushort(h0) | ((uint32_t)__bfloat16_as_ushort(h1) << 16);
    lp = (uint32_t)__bfloat16_as_ushort(l0) | ((uint32_t)__bfloat16_as_ushort(l1) << 16);
}

// ---------------------------------------------------------------------------
// Kernel 0: f32 -> split-bf16 pre-conversion (permuted layout)
// which: 0 = x, 1 = W_qkv, 2 = proj_W
// ---------------------------------------------------------------------------
__global__ void __launch_bounds__(256)
convert_split(const float* __restrict__ src, int which, int npairs)
{
    int i = blockIdx.x * 256 + threadIdx.x;
    if (i >= npairs) return;
    int row = i >> 10;         // KP_ = 1024
    int p = i & 1023;
    float2 v = *(const float2*)(src + (size_t)row * K_ + p * 2);
    uint32_t hp, lp;
    split_pack(v.x, v.y, hp, lp);
    int c = pair_perm(p);
    uint32_t* hi = (which == 0) ? g_xh : (which == 1) ? g_wh : g_pwh;
    uint32_t* lo = (which == 0) ? g_xl : (which == 1) ? g_wl : g_pwl;
    hi[(size_t)row * KP_ + c] = hp;
    lo[(size_t)row * KP_ + c] = lp;
}

// ---------------------------------------------------------------------------
// GEMM core: C[128x128] = A[128xK] * B[128xK]^T, split-bf16 (3 mma per k16).
// 256 threads = 8 warps (4m x 2n), warp tile 32x64.
// smem pitch PW=24 u32 -> conflict-free LDS.64 fragment loads.
// ---------------------------------------------------------------------------
#define PW 24

__device__ __forceinline__ void gemm_core_bf16s(
    const uint32_t* __restrict__ Ahg, const uint32_t* __restrict__ Alg,
    const uint32_t* __restrict__ Bhg, const uint32_t* __restrict__ Blg,
    int m0, int n0, uint32_t* sm, float acc[2][8][4], int tid)
{
    uint32_t* Ah = sm;
    uint32_t* Al = Ah + 128 * PW;
    uint32_t* Bh = Al + 128 * PW;
    uint32_t* Bl = Bh + 128 * PW;

    const int lane = tid & 31, wid = tid >> 5;
    const int g = lane >> 2, t = lane & 3;
    const int mw = (wid >> 1) * 32, nw = (wid & 1) * 64;

    const int r = tid >> 1;
    const int fq = (tid & 1) * 8;          // u32 offset within 16-u32 row block
    const bool aok = (m0 + r) < M_;
    const uint32_t* agh = Ahg + (size_t)(m0 + r) * KP_ + fq;
    const uint32_t* agl = Alg + (size_t)(m0 + r) * KP_ + fq;
    const uint32_t* bgh = Bhg + (size_t)(n0 + r) * KP_ + fq;
    const uint32_t* bgl = Blg + (size_t)(n0 + r) * KP_ + fq;

    const uint4 z4 = make_uint4(0u, 0u, 0u, 0u);
    uint4 pAh[2], pAl[2], pBh[2], pBl[2];
#pragma unroll
    for (int u = 0; u < 2; u++) {
        pAh[u] = aok ? *(const uint4*)(agh + 4 * u) : z4;
        pAl[u] = aok ? *(const uint4*)(agl + 4 * u) : z4;
        pBh[u] = *(const uint4*)(bgh + 4 * u);
        pBl[u] = *(const uint4*)(bgl + 4 * u);
    }

    for (int ku = 0; ku < KP_; ku += 16) {   // 16 u32 = BK 32
        __syncthreads();
#pragma unroll
        for (int u = 0; u < 2; u++) {
            *(uint4*)&Ah[r * PW + fq + 4 * u] = pAh[u];
            *(uint4*)&Al[r * PW + fq + 4 * u] = pAl[u];
            *(uint4*)&Bh[r * PW + fq + 4 * u] = pBh[u];
            *(uint4*)&Bl[r * PW + fq + 4 * u] = pBl[u];
        }
        __syncthreads();

        if (ku + 16 < KP_) {
#pragma unroll
            for (int u = 0; u < 2; u++) {
                pAh[u] = aok ? *(const uint4*)(agh + ku + 16 + 4 * u) : z4;
                pAl[u] = aok ? *(const uint4*)(agl + ku + 16 + 4 * u) : z4;
                pBh[u] = *(const uint4*)(bgh + ku + 16 + 4 * u);
                pBl[u] = *(const uint4*)(bgl + ku + 16 + 4 * u);
            }
        }

#pragma unroll
        for (int ks = 0; ks < 2; ks++) {
            uint32_t ah[2][4], al[2][4];
#pragma unroll
            for (int mi = 0; mi < 2; mi++) {
                int r0 = mw + 16 * mi + g;
                uint2 v0 = *(uint2*)&Ah[r0 * PW + ks * 8 + 2 * t];
                uint2 v1 = *(uint2*)&Ah[(r0 + 8) * PW + ks * 8 + 2 * t];
                ah[mi][0] = v0.x; ah[mi][2] = v0.y;
                ah[mi][1] = v1.x; ah[mi][3] = v1.y;
                uint2 w0 = *(uint2*)&Al[r0 * PW + ks * 8 + 2 * t];
                uint2 w1 = *(uint2*)&Al[(r0 + 8) * PW + ks * 8 + 2 * t];
                al[mi][0] = w0.x; al[mi][2] = w0.y;
                al[mi][1] = w1.x; al[mi][3] = w1.y;
            }
#pragma unroll
            for (int j = 0; j < 8; j++) {
                int cn = nw + 8 * j + g;
                uint2 bh = *(uint2*)&Bh[cn * PW + ks * 8 + 2 * t];
                uint2 bl = *(uint2*)&Bl[cn * PW + ks * 8 + 2 * t];
#pragma unroll
                for (int mi = 0; mi < 2; mi++) {
                    mma16(acc[mi][j], ah[mi][0], ah[mi][1], ah[mi][2], ah[mi][3], bh.x, bh.y);
                    mma16(acc[mi][j], ah[mi][0], ah[mi][1], ah[mi][2], ah[mi][3], bl.x, bl.y);
                    mma16(acc[mi][j], al[mi][0], al[mi][1], al[mi][2], al[mi][3], bh.x, bh.y);
                }
            }
        }
    }
}

// ---------------------------------------------------------------------------
// Kernel 1: QKV GEMM + scatter epilogue
// ---------------------------------------------------------------------------
__global__ void __launch_bounds__(256, 1)
qkv_gemm(const float* __restrict__ qb, const float* __restrict__ vb)
{
    extern __shared__ uint32_t smu[];
    float acc[2][8][4];
#pragma unroll
    for (int a = 0; a < 2; a++)
#pragma unroll
        for (int b = 0; b < 8; b++)
#pragma unroll
            for (int c = 0; c < 4; c++) acc[a][b][c] = 0.f;

    const int n0 = blockIdx.x * 128;
    const int m0 = blockIdx.y * 128;
    gemm_core_bf16s(g_xh, g_xl, g_wh, g_wl, m0, n0, smu, acc, threadIdx.x);

    const int lane = threadIdx.x & 31, wid = threadIdx.x >> 5;
    const int g = lane >> 2, t = lane & 3;
    const int mw = (wid >> 1) * 32, nw = (wid & 1) * 64;

    const int tq = n0 >> 11;                  // 0=q,1=k,2=v
    const int h = (n0 & 2047) >> 7;
    float* dst = (tq == 0) ? g_q : ((tq == 1) ? g_k : g_v);

    float2 bias[8];
#pragma unroll
    for (int j = 0; j < 8; j++) {
        int d = nw + 8 * j + 2 * t;
        float b0 = 0.f, b1 = 0.f;
        if (tq == 0) { b0 = qb[h * HD_ + d]; b1 = qb[h * HD_ + d + 1]; }
        else if (tq == 2) { b0 = vb[h * HD_ + d]; b1 = vb[h * HD_ + d + 1]; }
        bias[j] = make_float2(b0, b1);
    }

#pragma unroll
    for (int mi = 0; mi < 2; mi++)
#pragma unroll
        for (int rr = 0; rr < 2; rr++) {
            int gm = m0 + mw + 16 * mi + g + 8 * rr;
            if (gm >= M_) continue;
            int b = gm / L_;
            int l = gm - b * L_;
            float* p = dst + ((size_t)(b * H_ + h) * L_ + l) * HD_;
#pragma unroll
            for (int j = 0; j < 8; j++) {
                int d = nw + 8 * j + 2 * t;
                float2 o;
                o.x = acc[mi][j][2 * rr] + bias[j].x;
                o.y = acc[mi][j][2 * rr + 1] + bias[j].y;
                *(float2*)(p + d) = o;
            }
        }
}

// ---------------------------------------------------------------------------
// Kernel 2: norm + rope (fp32)
// ---------------------------------------------------------------------------
__global__ void __launch_bounds__(256)
norm_rope(const float* __restrict__ sml, const float* __restrict__ rope)
{
    const int gw = blockIdx.x * 8 + (threadIdx.x >> 5);
    const int lane = threadIdx.x & 31;
    if (gw >= B_ * H_ * L_) return;
    const int l = gw % L_;
    const int h = (gw / L_) % H_;

    float2 cc = *(const float2*)(rope + (size_t)l * 64 + lane * 2);
    float2 ss = *(const float2*)(rope + (size_t)L_ * 64 + (size_t)l * 64 + lane * 2);
    const float scale = __expf(fminf(sml[h], 4.605170185988091f));
    const size_t base = (size_t)gw * HD_ + lane * 4;

    {
        float4 v = *(const float4*)(g_q + base);
        float ssq = v.x * v.x + v.y * v.y + v.z * v.z + v.w * v.w;
#pragma unroll
        for (int o = 16; o; o >>= 1) ssq += __shfl_xor_sync(0xffffffffu, ssq, o);
        float inv = scale / fmaxf(sqrtf(ssq), 1e-12f);
        v.x *= inv; v.y *= inv; v.z *= inv; v.w *= inv;
        float4 r;
        r.x = cc.x * v.x - ss.x * v.y;
        r.y = ss.x * v.x + cc.x * v.y;
        r.z = cc.y * v.z - ss.y * v.w;
        r.w = ss.y * v.z + cc.y * v.w;
        *(float4*)(g_q + base) = r;
    }
    {
        float4 v = *(const float4*)(g_k + base);
        float ssq = v.x * v.x + v.y * v.y + v.z * v.z + v.w * v.w;
#pragma unroll
        for (int o = 16; o; o >>= 1) ssq += __shfl_xor_sync(0xffffffffu, ssq, o);
        float inv = 1.f / fmaxf(sqrtf(ssq), 1e-12f);
        v.x *= inv; v.y *= inv; v.z *= inv; v.w *= inv;
        float4 r;
        r.x = cc.x * v.x - ss.x * v.y;
        r.y = ss.x * v.x + cc.x * v.y;
        r.z = cc.y * v.z - ss.y * v.w;
        r.w = ss.y * v.z + cc.y * v.w;
        *(float4*)(g_k + base) = r;
    }
}

// ---------------------------------------------------------------------------
// Kernel 3: flash attention (tf32 mma), epilogue writes split-bf16 g_ao.
// ---------------------------------------------------------------------------
#define QTP 132
#define VTP 68

__device__ __forceinline__ int kend_of(int lq) {
    if (lq >= L_) return 0;
    int ke = 2521;
#pragma unroll
    for (int i = 9; i >= 0; i--)
        if (lq < d_cum[i]) ke = d_cum[i];
    return ke;
}

__global__ void __launch_bounds__(256, 1)
flash_attn()
{
    extern __shared__ float sm[];
    float* Qs  = sm;                       // [128][132]
    float* Ks  = Qs + 128 * QTP;           // [64][132]
    float* Vst = Ks + 64 * QTP;            // [128][68]
    float* Ps  = Vst + 128 * VTP;          // [128][68]

    const int bh = blockIdx.y;
    const int q0 = (gridDim.x - 1 - blockIdx.x) * 128;
    const float* qp = g_q + (size_t)bh * L_ * HD_;
    const float* kp = g_k + (size_t)bh * L_ * HD_;
    const float* vp = g_v + (size_t)bh * L_ * HD_;
    const int tid = threadIdx.x, lane = tid & 31, wid = tid >> 5;
    const int g = lane >> 2, t = lane & 3;

    {
        int r = tid >> 1, h64 = (tid & 1) * 64;
        const float* src = qp + (size_t)(q0 + r) * HD_ + h64;
        bool ok = (q0 + r) < L_;
#pragma unroll
        for (int i = 0; i < 16; i++) {
            float4 v = ok ? *(const float4*)(src + 4 * i) : make_float4(0.f, 0.f, 0.f, 0.f);
            float4 c;
            c.x = tf32r(v.x); c.y = tf32r(v.y); c.z = tf32r(v.z); c.w = tf32r(v.w);
            *(float4*)(Qs + r * QTP + h64 + 4 * i) = c;
        }
    }

    const int rowbase = wid * 16 + g;
    const int kend0 = kend_of(q0 + rowbase);
    const int kend1 = kend_of(q0 + rowbase + 8);
    int kmax;
    {
        int lql = min(q0 + 127, L_ - 1);
        kmax = 2521;
#pragma unroll
        for (int i = 9; i >= 0; i--)
            if (lql < d_cum[i]) kmax = d_cum[i];
    }

    float m0v = -1e30f, m1v = -1e30f, l0v = 0.f, l1v = 0.f;
    float O[16][4];
#pragma unroll
    for (int j = 0; j < 16; j++)
#pragma unroll
        for (int c = 0; c < 4; c++) O[j][c] = 0.f;

    for (int k0 = 0; k0 < kmax; k0 += 64) {
        __syncthreads();

        {
            int krow = tid >> 2, seg = (tid & 3) * 32;
            bool ok = (k0 + krow) < L_;
            const float* src = kp + (size_t)(k0 + krow) * HD_ + seg;
#pragma unroll
            for (int i = 0; i < 8; i++) {
                float4 v = ok ? *(const float4*)(src + 4 * i) : make_float4(0.f, 0.f, 0.f, 0.f);
                float4 c;
                c.x = tf32r(v.x); c.y = tf32r(v.y); c.z = tf32r(v.z); c.w = tf32r(v.w);
                *(float4*)(Ks + krow * QTP + seg + 4 * i) = c;
            }
        }
        {
            int vkey = tid & 63, vseg = (tid >> 6) * 32;
            bool ok = (k0 + vkey) < L_;
            const float* src = vp + (size_t)(k0 + vkey) * HD_ + vseg;
#pragma unroll
            for (int i = 0; i < 8; i++) {
                float4 v = ok ? *(const float4*)(src + 4 * i) : make_float4(0.f, 0.f, 0.f, 0.f);
                int c = vseg + 4 * i;
                Vst[(c + 0) * VTP + vkey] = tf32r(v.x);
                Vst[(c + 1) * VTP + vkey] = tf32r(v.y);
                Vst[(c + 2) * VTP + vkey] = tf32r(v.z);
                Vst[(c + 3) * VTP + vkey] = tf32r(v.w);
            }
        }
        __syncthreads();

        float sc[8][4];
#pragma unroll
        for (int j = 0; j < 8; j++)
#pragma unroll
            for (int c = 0; c < 4; c++) sc[j][c] = 0.f;

#pragma unroll
        for (int kk = 0; kk < 128; kk += 8) {
            uint32_t a0 = __float_as_uint(Qs[rowbase * QTP + kk + t]);
            uint32_t a1 = __float_as_uint(Qs[(rowbase + 8) * QTP + kk + t]);
            uint32_t a2 = __float_as_uint(Qs[rowbase * QTP + kk + t + 4]);
            uint32_t a3 = __float_as_uint(Qs[(rowbase + 8) * QTP + kk + t + 4]);
#pragma unroll
            for (int j = 0; j < 8; j++) {
                uint32_t b0 = __float_as_uint(Ks[(8 * j + g) * QTP + kk + t]);
                uint32_t b1 = __float_as_uint(Ks[(8 * j + g) * QTP + kk + t + 4]);
                mma8(sc[j], a0, a1, a2, a3, b0, b1);
            }
        }

        float rmax0 = -1e30f, rmax1 = -1e30f;
#pragma unroll
        for (int j = 0; j < 8; j++) {
            int c0 = k0 + 8 * j + 2 * t, c1 = c0 + 1;
            if (c0 >= kend0) sc[j][0] = -1e30f;
            if (c1 >= kend0) sc[j][1] = -1e30f;
            if (c0 >= kend1) sc[j][2] = -1e30f;
            if (c1 >= kend1) sc[j][3] = -1e30f;
            rmax0 = fmaxf(rmax0, fmaxf(sc[j][0], sc[j][1]));
            rmax1 = fmaxf(rmax1, fmaxf(sc[j][2], sc[j][3]));
        }
        rmax0 = fmaxf(rmax0, __shfl_xor_sync(0xffffffffu, rmax0, 1));
        rmax0 = fmaxf(rmax0, __shfl_xor_sync(0xffffffffu, rmax0, 2));
        rmax1 = fmaxf(rmax1, __shfl_xor_sync(0xffffffffu, rmax1, 1));
        rmax1 = fmaxf(rmax1, __shfl_xor_sync(0xffffffffu, rmax1, 2));

        float mn0 = fmaxf(m0v, rmax0), mn1 = fmaxf(m1v, rmax1);
        float al0 = __expf(m0v - mn0), al1 = __expf(m1v - mn1);
        float rs0 = 0.f, rs1 = 0.f;
#pragma unroll
        for (int j = 0; j < 8; j++) {
            float p0 = (sc[j][0] > -5e29f) ? __expf(sc[j][0] - mn0) : 0.f;
            float p1 = (sc[j][1] > -5e29f) ? __expf(sc[j][1] - mn0) : 0.f;
            float p2 = (sc[j][2] > -5e29f) ? __expf(sc[j][2] - mn1) : 0.f;
            float p3 = (sc[j][3] > -5e29f) ? __expf(sc[j][3] - mn1) : 0.f;
            rs0 += p0 + p1;
            rs1 += p2 + p3;
            int col = 8 * j + 2 * t;
            *(float2*)(Ps + rowbase * VTP + col) = make_float2(tf32r(p0), tf32r(p1));
            *(float2*)(Ps + (rowbase + 8) * VTP + col) = make_float2(tf32r(p2), tf32r(p3));
        }
        rs0 += __shfl_xor_sync(0xffffffffu, rs0, 1);
        rs0 += __shfl_xor_sync(0xffffffffu, rs0, 2);
        rs1 += __shfl_xor_sync(0xffffffffu, rs1, 1);
        rs1 += __shfl_xor_sync(0xffffffffu, rs1, 2);
        l0v = l0v * al0 + rs0;
        l1v = l1v * al1 + rs1;
        m0v = mn0; m1v = mn1;

#pragma unroll
        for (int j = 0; j < 16; j++) {
            O[j][0] *= al0; O[j][1] *= al0;
            O[j][2] *= al1; O[j][3] *= al1;
        }
        __syncthreads();

#pragma unroll
        for (int kk = 0; kk < 64; kk += 8) {
            uint32_t a0 = __float_as_uint(Ps[rowbase * VTP + kk + t]);
            uint32_t a1 = __float_as_uint(Ps[(rowbase + 8) * VTP + kk + t]);
            uint32_t a2 = __float_as_uint(Ps[rowbase * VTP + kk + t + 4]);
            uint32_t a3 = __float_as_uint(Ps[(rowbase + 8) * VTP + kk + t + 4]);
#pragma unroll
            for (int j = 0; j < 16; j++) {
                uint32_t b0 = __float_as_uint(Vst[(8 * j + g) * VTP + kk + t]);
                uint32_t b1 = __float_as_uint(Vst[(8 * j + g) * VTP + kk + t + 4]);
                mma8(O[j], a0, a1, a2, a3, b0, b1);
            }
        }
    }

    // epilogue: normalize, convert to split-bf16 pairs, write permuted layout
    const int b = bh >> 4;
    const int h = bh & 15;
#pragma unroll
    for (int rr = 0; rr < 2; rr++) {
        int lq = q0 + rowbase + 8 * rr;
        if (lq >= L_) continue;
        float inv = 1.f / (rr ? l1v : l0v);
        size_t rowoff = (size_t)(b * L_ + lq) * KP_;
#pragma unroll
        for (int j = 0; j < 16; j++) {
            float x0 = O[j][2 * rr] * inv;
            float x1 = O[j][2 * rr + 1] * inv;
            uint32_t hp, lp;
            split_pack(x0, x1, hp, lp);
            int p = h * 64 + 4 * j + t;
            int c = pair_perm(p);
            g_aoh[rowoff + c] = hp;
            g_aol[rowoff + c] = lp;
        }
    }
}

// ---------------------------------------------------------------------------
// Kernel 4: projection GEMM
// ---------------------------------------------------------------------------
__global__ void __launch_bounds__(256, 1)
proj_gemm(const float* __restrict__ pb, float* __restrict__ out)
{
    extern __shared__ uint32_t smu[];
    float acc[2][8][4];
#pragma unroll
    for (int a = 0; a < 2; a++)
#pragma unroll
        for (int b = 0; b < 8; b++)
#pragma unroll
            for (int c = 0; c < 4; c++) acc[a][b][c] = 0.f;

    const int n0 = blockIdx.x * 128;
    const int m0 = blockIdx.y * 128;
    gemm_core_bf16s(g_aoh, g_aol, g_pwh, g_pwl, m0, n0, smu, acc, threadIdx.x);

    const int lane = threadIdx.x & 31, wid = threadIdx.x >> 5;
    const int g = lane >> 2, t = lane & 3;
    const int mw = (wid >> 1) * 32, nw = (wid & 1) * 64;

    float2 bias[8];
#pragma unroll
    for (int j = 0; j < 8; j++) {
        int n = n0 + nw + 8 * j + 2 * t;
        bias[j] = make_float2(pb[n], pb[n + 1]);
    }

#pragma unroll
    for (int mi = 0; mi < 2; mi++)
#pragma unroll
        for (int rr = 0; rr < 2; rr++) {
            int gm = m0 + mw + 16 * mi + g + 8 * rr;
            if (gm >= M_) continue;
            float* p = out + (size_t)gm * C_ + n0 + nw;
#pragma unroll
            for (int j = 0; j < 8; j++) {
                float2 o;
                o.x = acc[mi][j][2 * rr] + bias[j].x;
                o.y = acc[mi][j][2 * rr + 1] + bias[j].y;
                *(float2*)(p + 8 * j + 2 * t) = o;
            }
        }
}

// ---------------------------------------------------------------------------
// launch
// ---------------------------------------------------------------------------
extern "C" void kernel_launch(void* const* d_in, const int* in_sizes, int n_in,
                              void* d_out, int out_size)
{
    const float* x    = (const float*)d_in[0];
    const float* Wqkv = (const float*)d_in[1];
    const float* qb   = (const float*)d_in[2];
    const float* vb   = (const float*)d_in[3];
    const float* sml  = (const float*)d_in[4];
    const float* pW   = (const float*)d_in[5];
    const float* pb   = (const float*)d_in[6];
    const float* rope = (const float*)d_in[7];
    float* out = (float*)d_out;

    const size_t gemm_shm = (size_t)4 * 128 * PW * sizeof(uint32_t);   // 49,152 B
    const size_t flash_shm = (size_t)(128 * QTP + 64 * QTP + 128 * VTP + 128 * VTP) * sizeof(float);

    cudaFuncSetAttribute(qkv_gemm, cudaFuncAttributeMaxDynamicSharedMemorySize, (int)gemm_shm);
    cudaFuncSetAttribute(proj_gemm, cudaFuncAttributeMaxDynamicSharedMemorySize, (int)gemm_shm);
    cudaFuncSetAttribute(flash_attn, cudaFuncAttributeMaxDynamicSharedMemorySize, (int)flash_shm);

    // pre-convert inputs to split-bf16 (permuted pair layout)
    {
        int np;
        np = M_ * KP_;    convert_split<<<(np + 255) / 256, 256>>>(x, 0, np);
        np = NQKV * KP_;  convert_split<<<(np + 255) / 256, 256>>>(Wqkv, 1, np);
        np = C_ * KP_;    convert_split<<<(np + 255) / 256, 256>>>(pW, 2, np);
    }

    dim3 g1(NQKV / 128, (M_ + 127) / 128);   // 48 x 40
    qkv_gemm<<<g1, 256, gemm_shm>>>(qb, vb);

    int nwarps = B_ * H_ * L_;
    norm_rope<<<(nwarps + 7) / 8, 256>>>(sml, rope);

    dim3 g3((L_ + 127) / 128, B_ * H_);      // 20 x 32
    flash_attn<<<g3, 256, flash_shm>>>();

    dim3 g4(C_ / 128, (M_ + 127) / 128);     // 16 x 40
    proj_gemm<<<g4, 256, gemm_shm>>>(pb, out);
}

// round 5
// speedup vs baseline: 2.2734x; 1.1508x over previous
#include <cuda_runtime.h>
#include <cuda_bf16.h>
#include <cstdint>
#include <math.h>

// ---------------------------------------------------------------------------
// Problem constants
// ---------------------------------------------------------------------------
#define B_   2
#define L_   2521
#define C_   2048
#define H_   16
#define HD_  128
#define M_   (B_ * L_)          // 5042
#define K_   2048
#define KP_  1024               // K/2 u32 pairs per row
#define NQKV 6144

__device__ __constant__ int d_cum[10] = {1, 5, 21, 57, 121, 265, 521, 921, 1497, 2521};

// f32 scratch (q/k/v stored pre-rounded to tf32 bit patterns)
__device__ float g_q[B_ * H_ * L_ * HD_];
__device__ float g_k[B_ * H_ * L_ * HD_];
__device__ float g_v[B_ * H_ * L_ * HD_];

// split-bf16 scratch (u32 = packed bf16x2, pair-permuted layout)
__device__ uint32_t g_xh[M_ * KP_],   g_xl[M_ * KP_];
__device__ uint32_t g_wh[NQKV * KP_], g_wl[NQKV * KP_];
__device__ uint32_t g_pwh[C_ * KP_],  g_pwl[C_ * KP_];
__device__ uint32_t g_aoh[M_ * KP_],  g_aol[M_ * KP_];

// ---------------------------------------------------------------------------
// helpers
// ---------------------------------------------------------------------------
__device__ __forceinline__ uint32_t f2tf(float x) {
    uint32_t r;
    asm("cvt.rna.tf32.f32 %0, %1;" : "=r"(r) : "f"(x));
    return r;
}
__device__ __forceinline__ float tf32r(float x) { return __uint_as_float(f2tf(x)); }

__device__ __forceinline__ void mma8(float* c,
                                     uint32_t a0, uint32_t a1, uint32_t a2, uint32_t a3,
                                     uint32_t b0, uint32_t b1)
{
    asm volatile(
        "mma.sync.aligned.m16n8k8.row.col.f32.tf32.tf32.f32 "
        "{%0,%1,%2,%3}, {%4,%5,%6,%7}, {%8,%9}, {%0,%1,%2,%3};"
        : "+f"(c[0]), "+f"(c[1]), "+f"(c[2]), "+f"(c[3])
        : "r"(a0), "r"(a1), "r"(a2), "r"(a3), "r"(b0), "r"(b1));
}

__device__ __forceinline__ void mma16(float* c,
                                      uint32_t a0, uint32_t a1, uint32_t a2, uint32_t a3,
                                      uint32_t b0, uint32_t b1)
{
    asm volatile(
        "mma.sync.aligned.m16n8k16.row.col.f32.bf16.bf16.f32 "
        "{%0,%1,%2,%3}, {%4,%5,%6,%7}, {%8,%9}, {%0,%1,%2,%3};"
        : "+f"(c[0]), "+f"(c[1]), "+f"(c[2]), "+f"(c[3])
        : "r"(a0), "r"(a1), "r"(a2), "r"(a3), "r"(b0), "r"(b1));
}

__device__ __forceinline__ uint32_t smaddr(const void* p) {
    return (uint32_t)__cvta_generic_to_shared(p);
}
__device__ __forceinline__ void cp16(uint32_t dst, const void* src, bool pred) {
    int sz = pred ? 16 : 0;
    asm volatile("cp.async.cg.shared.global [%0], [%1], 16, %2;"
                 :: "r"(dst), "l"(src), "r"(sz));
}
__device__ __forceinline__ void cp_commit() {
    asm volatile("cp.async.commit_group;");
}
template<int N>
__device__ __forceinline__ void cp_wait() {
    asm volatile("cp.async.wait_group %0;" :: "n"(N));
}

// permuted pair column for split-bf16 GEMM fragments
__device__ __forceinline__ int pair_perm(int p) {
    int q = p & 15;
    return (p & ~15) + (q & 8) + (q & 3) * 2 + ((q >> 2) & 1);
}

__device__ __forceinline__ void split_pack(float x0, float x1, uint32_t& hp, uint32_t& lp) {
    __nv_bfloat16 h0 = __float2bfloat16_rn(x0);
    __nv_bfloat16 h1 = __float2bfloat16_rn(x1);
    float l0f = x0 - __bfloat162float(h0);
    float l1f = x1 - __bfloat162float(h1);
    __nv_bfloat16 l0 = __float2bfloat16_rn(l0f);
    __nv_bfloat16 l1 = __float2bfloat16_rn(l1f);
    hp = (uint32_t)__bfloat16_as_ushort(h0) | ((uint32_t)__bfloat16_as_ushort(h1) << 16);
    lp = (uint32_t)__bfloat16_as_ushort(l0) | ((uint32_t)__bfloat16_as_ushort(l1) << 16);
}

// ---------------------------------------------------------------------------
// Kernel 0: f32 -> split-bf16 pre-conversion (permuted layout)
// ---------------------------------------------------------------------------
__global__ void __launch_bounds__(256)
convert_split(const float* __restrict__ src, int which, int npairs)
{
    int i = blockIdx.x * 256 + threadIdx.x;
    if (i >= npairs) return;
    int row = i >> 10;
    int p = i & 1023;
    float2 v = *(const float2*)(src + (size_t)row * K_ + p * 2);
    uint32_t hp, lp;
    split_pack(v.x, v.y, hp, lp);
    int c = pair_perm(p);
    uint32_t* hi = (which == 0) ? g_xh : (which == 1) ? g_wh : g_pwh;
    uint32_t* lo = (which == 0) ? g_xl : (which == 1) ? g_wl : g_pwl;
    hi[(size_t)row * KP_ + c] = hp;
    lo[(size_t)row * KP_ + c] = lp;
}

// ---------------------------------------------------------------------------
// GEMM core: split-bf16, cp.async double-buffered, BK=32 (16 u32).
// Stage = 4 arrays x 128 rows x PW u32.
// ---------------------------------------------------------------------------
#define PW 24
#define GSTAGE (4 * 128 * PW)    // u32 per stage = 12288 (49152 B)

__device__ __forceinline__ void gemm_prefetch(
    uint32_t* stage_base, const uint32_t* agh, const uint32_t* agl,
    const uint32_t* bgh, const uint32_t* bgl, int ku, bool aok, int r, int fq)
{
    uint32_t dA = smaddr(stage_base + r * PW + fq);
    cp16(dA,      agh + ku,     aok);
    cp16(dA + 16, agh + ku + 4, aok);
    uint32_t dAl = dA + 128 * PW * 4;
    cp16(dAl,      agl + ku,     aok);
    cp16(dAl + 16, agl + ku + 4, aok);
    uint32_t dB = dAl + 128 * PW * 4;
    cp16(dB,      bgh + ku,     true);
    cp16(dB + 16, bgh + ku + 4, true);
    uint32_t dBl = dB + 128 * PW * 4;
    cp16(dBl,      bgl + ku,     true);
    cp16(dBl + 16, bgl + ku + 4, true);
}

__device__ __forceinline__ void gemm_core_bf16s(
    const uint32_t* __restrict__ Ahg, const uint32_t* __restrict__ Alg,
    const uint32_t* __restrict__ Bhg, const uint32_t* __restrict__ Blg,
    int m0, int n0, uint32_t* sm, float acc[2][8][4], int tid)
{
    const int lane = tid & 31, wid = tid >> 5;
    const int g = lane >> 2, t = lane & 3;
    const int mw = (wid >> 1) * 32, nw = (wid & 1) * 64;

    const int r = tid >> 1;
    const int fq = (tid & 1) * 8;
    const bool aok = (m0 + r) < M_;
    const int arow = aok ? (m0 + r) : 0;
    const uint32_t* agh = Ahg + (size_t)arow * KP_ + fq;
    const uint32_t* agl = Alg + (size_t)arow * KP_ + fq;
    const uint32_t* bgh = Bhg + (size_t)(n0 + r) * KP_ + fq;
    const uint32_t* bgl = Blg + (size_t)(n0 + r) * KP_ + fq;

    gemm_prefetch(sm, agh, agl, bgh, bgl, 0, aok, r, fq);
    cp_commit();

    const int NIT = KP_ / 16;    // 64
    for (int it = 0; it < NIT; it++) {
        if (it + 1 < NIT) {
            gemm_prefetch(sm + ((it + 1) & 1) * GSTAGE, agh, agl, bgh, bgl,
                          (it + 1) * 16, aok, r, fq);
            cp_commit();
            cp_wait<1>();
        } else {
            cp_wait<0>();
        }
        __syncthreads();

        uint32_t* Ah = sm + (it & 1) * GSTAGE;
        uint32_t* Al = Ah + 128 * PW;
        uint32_t* Bh = Al + 128 * PW;
        uint32_t* Bl = Bh + 128 * PW;

#pragma unroll
        for (int ks = 0; ks < 2; ks++) {
            uint32_t ah[2][4], al[2][4];
#pragma unroll
            for (int mi = 0; mi < 2; mi++) {
                int r0 = mw + 16 * mi + g;
                uint2 v0 = *(uint2*)&Ah[r0 * PW + ks * 8 + 2 * t];
                uint2 v1 = *(uint2*)&Ah[(r0 + 8) * PW + ks * 8 + 2 * t];
                ah[mi][0] = v0.x; ah[mi][2] = v0.y;
                ah[mi][1] = v1.x; ah[mi][3] = v1.y;
                uint2 w0 = *(uint2*)&Al[r0 * PW + ks * 8 + 2 * t];
                uint2 w1 = *(uint2*)&Al[(r0 + 8) * PW + ks * 8 + 2 * t];
                al[mi][0] = w0.x; al[mi][2] = w0.y;
                al[mi][1] = w1.x; al[mi][3] = w1.y;
            }
#pragma unroll
            for (int j = 0; j < 8; j++) {
                int cn = nw + 8 * j + g;
                uint2 bh = *(uint2*)&Bh[cn * PW + ks * 8 + 2 * t];
                uint2 bl = *(uint2*)&Bl[cn * PW + ks * 8 + 2 * t];
#pragma unroll
                for (int mi = 0; mi < 2; mi++) {
                    mma16(acc[mi][j], ah[mi][0], ah[mi][1], ah[mi][2], ah[mi][3], bh.x, bh.y);
                    mma16(acc[mi][j], ah[mi][0], ah[mi][1], ah[mi][2], ah[mi][3], bl.x, bl.y);
                    mma16(acc[mi][j], al[mi][0], al[mi][1], al[mi][2], al[mi][3], bh.x, bh.y);
                }
            }
        }
        __syncthreads();
    }
}

// ---------------------------------------------------------------------------
// Kernel 1: QKV GEMM + scatter epilogue (V pre-rounded to tf32)
// ---------------------------------------------------------------------------
__global__ void __launch_bounds__(256, 2)
qkv_gemm(const float* __restrict__ qb, const float* __restrict__ vb)
{
    extern __shared__ uint32_t smu[];
    float acc[2][8][4];
#pragma unroll
    for (int a = 0; a < 2; a++)
#pragma unroll
        for (int b = 0; b < 8; b++)
#pragma unroll
            for (int c = 0; c < 4; c++) acc[a][b][c] = 0.f;

    const int n0 = blockIdx.x * 128;
    const int m0 = blockIdx.y * 128;
    gemm_core_bf16s(g_xh, g_xl, g_wh, g_wl, m0, n0, smu, acc, threadIdx.x);

    const int lane = threadIdx.x & 31, wid = threadIdx.x >> 5;
    const int g = lane >> 2, t = lane & 3;
    const int mw = (wid >> 1) * 32, nw = (wid & 1) * 64;

    const int tq = n0 >> 11;
    const int h = (n0 & 2047) >> 7;
    float* dst = (tq == 0) ? g_q : ((tq == 1) ? g_k : g_v);

    float2 bias[8];
#pragma unroll
    for (int j = 0; j < 8; j++) {
        int d = nw + 8 * j + 2 * t;
        float b0 = 0.f, b1 = 0.f;
        if (tq == 0) { b0 = qb[h * HD_ + d]; b1 = qb[h * HD_ + d + 1]; }
        else if (tq == 2) { b0 = vb[h * HD_ + d]; b1 = vb[h * HD_ + d + 1]; }
        bias[j] = make_float2(b0, b1);
    }

#pragma unroll
    for (int mi = 0; mi < 2; mi++)
#pragma unroll
        for (int rr = 0; rr < 2; rr++) {
            int gm = m0 + mw + 16 * mi + g + 8 * rr;
            if (gm >= M_) continue;
            int b = gm / L_;
            int l = gm - b * L_;
            float* p = dst + ((size_t)(b * H_ + h) * L_ + l) * HD_;
#pragma unroll
            for (int j = 0; j < 8; j++) {
                int d = nw + 8 * j + 2 * t;
                float2 o;
                o.x = acc[mi][j][2 * rr] + bias[j].x;
                o.y = acc[mi][j][2 * rr + 1] + bias[j].y;
                if (tq == 2) { o.x = tf32r(o.x); o.y = tf32r(o.y); }  // V: pre-round
                *(float2*)(p + d) = o;
            }
        }
}

// ---------------------------------------------------------------------------
// Kernel 2: norm + rope, outputs pre-rounded to tf32
// ---------------------------------------------------------------------------
__global__ void __launch_bounds__(256)
norm_rope(const float* __restrict__ sml, const float* __restrict__ rope)
{
    const int gw = blockIdx.x * 8 + (threadIdx.x >> 5);
    const int lane = threadIdx.x & 31;
    if (gw >= B_ * H_ * L_) return;
    const int l = gw % L_;
    const int h = (gw / L_) % H_;

    float2 cc = *(const float2*)(rope + (size_t)l * 64 + lane * 2);
    float2 ss = *(const float2*)(rope + (size_t)L_ * 64 + (size_t)l * 64 + lane * 2);
    const float scale = __expf(fminf(sml[h], 4.605170185988091f));
    const size_t base = (size_t)gw * HD_ + lane * 4;

    {
        float4 v = *(const float4*)(g_q + base);
        float ssq = v.x * v.x + v.y * v.y + v.z * v.z + v.w * v.w;
#pragma unroll
        for (int o = 16; o; o >>= 1) ssq += __shfl_xor_sync(0xffffffffu, ssq, o);
        float inv = scale / fmaxf(sqrtf(ssq), 1e-12f);
        v.x *= inv; v.y *= inv; v.z *= inv; v.w *= inv;
        float4 r;
        r.x = tf32r(cc.x * v.x - ss.x * v.y);
        r.y = tf32r(ss.x * v.x + cc.x * v.y);
        r.z = tf32r(cc.y * v.z - ss.y * v.w);
        r.w = tf32r(ss.y * v.z + cc.y * v.w);
        *(float4*)(g_q + base) = r;
    }
    {
        float4 v = *(const float4*)(g_k + base);
        float ssq = v.x * v.x + v.y * v.y + v.z * v.z + v.w * v.w;
#pragma unroll
        for (int o = 16; o; o >>= 1) ssq += __shfl_xor_sync(0xffffffffu, ssq, o);
        float inv = 1.f / fmaxf(sqrtf(ssq), 1e-12f);
        v.x *= inv; v.y *= inv; v.z *= inv; v.w *= inv;
        float4 r;
        r.x = tf32r(cc.x * v.x - ss.x * v.y);
        r.y = tf32r(ss.x * v.x + cc.x * v.y);
        r.z = tf32r(cc.y * v.z - ss.y * v.w);
        r.w = tf32r(ss.y * v.z + cc.y * v.w);
        *(float4*)(g_k + base) = r;
    }
}

// ---------------------------------------------------------------------------
// Kernel 3: flash attention.
// Q fragments register-resident; P stays in registers (V rows permuted so
// S-output fragments ARE the PV A-fragments); cp.async double-buffered K/V.
// ---------------------------------------------------------------------------
#define FKP 132                       // K tile pitch (floats), == 4 mod 32
#define FVP 136                       // V tile pitch (floats), == 8 mod 32
#define FSTAGE (64 * FKP + 64 * FVP)  // floats per K+V stage = 17152 (68608 B)

__device__ __forceinline__ int kend_of(int lq) {
    if (lq >= L_) return 0;
    int ke = 2521;
#pragma unroll
    for (int i = 9; i >= 0; i--)
        if (lq < d_cum[i]) ke = d_cum[i];
    return ke;
}

__device__ __forceinline__ void flash_prefetch(
    float* sm, int s, int k0, const float* kp, const float* vp, int tid)
{
    float* Kb = sm + s * FSTAGE;
    float* Vb = Kb + 64 * FKP;
    int kr = tid >> 2;                 // key row 0..63
    int cb = (tid & 3) * 32;           // float col base
    bool ok = (k0 + kr) < L_;
    const float* ks = kp + (size_t)(ok ? (k0 + kr) : 0) * HD_ + cb;
    uint32_t dK = smaddr(Kb + kr * FKP + cb);
#pragma unroll
    for (int i = 0; i < 8; i++) cp16(dK + 16 * i, ks + 4 * i, ok);
    // V row permutation: within each 8-key group, key k -> slot (k>>1) + ((k&1)<<2)
    int w = kr & 7;
    int slot = (kr & ~7) + (w >> 1) + ((w & 1) << 2);
    const float* vs = vp + (size_t)(ok ? (k0 + kr) : 0) * HD_ + cb;
    uint32_t dV = smaddr(Vb + slot * FVP + cb);
#pragma unroll
    for (int i = 0; i < 8; i++) cp16(dV + 16 * i, vs + 4 * i, ok);
}

__global__ void __launch_bounds__(256, 1)
flash_attn()
{
    extern __shared__ float sm[];

    const int bh = blockIdx.y;
    const int q0 = (gridDim.x - 1 - blockIdx.x) * 128;
    const float* qp = g_q + (size_t)bh * L_ * HD_;
    const float* kp = g_k + (size_t)bh * L_ * HD_;
    const float* vp = g_v + (size_t)bh * L_ * HD_;
    const int tid = threadIdx.x, lane = tid & 31, wid = tid >> 5;
    const int g = lane >> 2, t = lane & 3;
    const int rowbase = wid * 16 + g;

    // stage Q tile into smem (overlaps K/V buffers; consumed before first prefetch)
    {
        int r = tid >> 1;
        int cb = (tid & 1) * 64;
        bool ok = (q0 + r) < L_;
        const float* src = qp + (size_t)(ok ? (q0 + r) : 0) * HD_ + cb;
        uint32_t d = smaddr(sm + r * FKP + cb);
#pragma unroll
        for (int i = 0; i < 16; i++) cp16(d + 16 * i, src + 4 * i, ok);
    }
    cp_commit();
    cp_wait<0>();
    __syncthreads();

    // extract Q fragments (loop-invariant over k-tiles)
    uint32_t qf[16][4];
#pragma unroll
    for (int kk8 = 0; kk8 < 16; kk8++) {
        int kk = kk8 * 8;
        qf[kk8][0] = __float_as_uint(sm[rowbase * FKP + kk + t]);
        qf[kk8][1] = __float_as_uint(sm[(rowbase + 8) * FKP + kk + t]);
        qf[kk8][2] = __float_as_uint(sm[rowbase * FKP + kk + t + 4]);
        qf[kk8][3] = __float_as_uint(sm[(rowbase + 8) * FKP + kk + t + 4]);
    }
    __syncthreads();

    const int kend0 = kend_of(q0 + rowbase);
    const int kend1 = kend_of(q0 + rowbase + 8);
    int kmax;
    {
        int lql = min(q0 + 127, L_ - 1);
        kmax = 2521;
#pragma unroll
        for (int i = 9; i >= 0; i--)
            if (lql < d_cum[i]) kmax = d_cum[i];
    }
    const int niter = (kmax + 63) / 64;

    float m0v = -1e30f, m1v = -1e30f, l0v = 0.f, l1v = 0.f;
    float O[16][4];
#pragma unroll
    for (int j = 0; j < 16; j++)
#pragma unroll
        for (int c = 0; c < 4; c++) O[j][c] = 0.f;

    flash_prefetch(sm, 0, 0, kp, vp, tid);
    cp_commit();

    for (int it = 0; it < niter; it++) {
        const int k0 = it * 64;
        if (it + 1 < niter) {
            flash_prefetch(sm, (it + 1) & 1, k0 + 64, kp, vp, tid);
            cp_commit();
            cp_wait<1>();
        } else {
            cp_wait<0>();
        }
        __syncthreads();

        float* Kb = sm + (it & 1) * FSTAGE;
        float* Vb = Kb + 64 * FKP;

        // S = Q K^T
        float sc[8][4];
#pragma unroll
        for (int j = 0; j < 8; j++)
#pragma unroll
            for (int c = 0; c < 4; c++) sc[j][c] = 0.f;

#pragma unroll
        for (int kk8 = 0; kk8 < 16; kk8++) {
            int kk = kk8 * 8;
#pragma unroll
            for (int j = 0; j < 8; j++) {
                uint32_t b0 = __float_as_uint(Kb[(8 * j + g) * FKP + kk + t]);
                uint32_t b1 = __float_as_uint(Kb[(8 * j + g) * FKP + kk + t + 4]);
                mma8(sc[j], qf[kk8][0], qf[kk8][1], qf[kk8][2], qf[kk8][3], b0, b1);
            }
        }

        // mask + online softmax
        float rmax0 = -1e30f, rmax1 = -1e30f;
#pragma unroll
        for (int j = 0; j < 8; j++) {
            int c0 = k0 + 8 * j + 2 * t, c1 = c0 + 1;
            if (c0 >= kend0) sc[j][0] = -1e30f;
            if (c1 >= kend0) sc[j][1] = -1e30f;
            if (c0 >= kend1) sc[j][2] = -1e30f;
            if (c1 >= kend1) sc[j][3] = -1e30f;
            rmax0 = fmaxf(rmax0, fmaxf(sc[j][0], sc[j][1]));
            rmax1 = fmaxf(rmax1, fmaxf(sc[j][2], sc[j][3]));
        }
        rmax0 = fmaxf(rmax0, __shfl_xor_sync(0xffffffffu, rmax0, 1));
        rmax0 = fmaxf(rmax0, __shfl_xor_sync(0xffffffffu, rmax0, 2));
        rmax1 = fmaxf(rmax1, __shfl_xor_sync(0xffffffffu, rmax1, 1));
        rmax1 = fmaxf(rmax1, __shfl_xor_sync(0xffffffffu, rmax1, 2));

        float mn0 = fmaxf(m0v, rmax0), mn1 = fmaxf(m1v, rmax1);
        float al0 = __expf(m0v - mn0), al1 = __expf(m1v - mn1);
        float rs0 = 0.f, rs1 = 0.f;
#pragma unroll
        for (int j = 0; j < 8; j++) {
            float p0 = (sc[j][0] > -5e29f) ? __expf(sc[j][0] - mn0) : 0.f;
            float p1 = (sc[j][1] > -5e29f) ? __expf(sc[j][1] - mn0) : 0.f;
            float p2 = (sc[j][2] > -5e29f) ? __expf(sc[j][2] - mn1) : 0.f;
            float p3 = (sc[j][3] > -5e29f) ? __expf(sc[j][3] - mn1) : 0.f;
            rs0 += p0 + p1;
            rs1 += p2 + p3;
            sc[j][0] = p0; sc[j][1] = p1; sc[j][2] = p2; sc[j][3] = p3;
        }
        rs0 += __shfl_xor_sync(0xffffffffu, rs0, 1);
        rs0 += __shfl_xor_sync(0xffffffffu, rs0, 2);
        rs1 += __shfl_xor_sync(0xffffffffu, rs1, 1);
        rs1 += __shfl_xor_sync(0xffffffffu, rs1, 2);
        l0v = l0v * al0 + rs0;
        l1v = l1v * al1 + rs1;
        m0v = mn0; m1v = mn1;

#pragma unroll
        for (int j = 0; j < 16; j++) {
            O[j][0] *= al0; O[j][1] *= al0;
            O[j][2] *= al1; O[j][3] *= al1;
        }

        // O += P V  — P fed straight from sc registers (V rows pre-permuted
        // so mma k-slot t <-> P column 2t, slot t+4 <-> column 2t+1)
#pragma unroll
        for (int c = 0; c < 8; c++) {
            uint32_t a0 = f2tf(sc[c][0]);
            uint32_t a1 = f2tf(sc[c][2]);
            uint32_t a2 = f2tf(sc[c][1]);
            uint32_t a3 = f2tf(sc[c][3]);
            const float* v0 = Vb + (8 * c + t) * FVP + g;
            const float* v1 = Vb + (8 * c + t + 4) * FVP + g;
#pragma unroll
            for (int j = 0; j < 16; j++) {
                uint32_t b0 = __float_as_uint(v0[8 * j]);
                uint32_t b1 = __float_as_uint(v1[8 * j]);
                mma8(O[j], a0, a1, a2, a3, b0, b1);
            }
        }
        __syncthreads();
    }

    // epilogue: normalize, convert to split-bf16 pairs, write permuted layout
    const int b = bh >> 4;
    const int h = bh & 15;
#pragma unroll
    for (int rr = 0; rr < 2; rr++) {
        int lq = q0 + rowbase + 8 * rr;
        if (lq >= L_) continue;
        float inv = 1.f / (rr ? l1v : l0v);
        size_t rowoff = (size_t)(b * L_ + lq) * KP_;
#pragma unroll
        for (int j = 0; j < 16; j++) {
            float x0 = O[j][2 * rr] * inv;
            float x1 = O[j][2 * rr + 1] * inv;
            uint32_t hp, lp;
            split_pack(x0, x1, hp, lp);
            int p = h * 64 + 4 * j + t;
            int c = pair_perm(p);
            g_aoh[rowoff + c] = hp;
            g_aol[rowoff + c] = lp;
        }
    }
}

// ---------------------------------------------------------------------------
// Kernel 4: projection GEMM
// ---------------------------------------------------------------------------
__global__ void __launch_bounds__(256, 2)
proj_gemm(const float* __restrict__ pb, float* __restrict__ out)
{
    extern __shared__ uint32_t smu[];
    float acc[2][8][4];
#pragma unroll
    for (int a = 0; a < 2; a++)
#pragma unroll
        for (int b = 0; b < 8; b++)
#pragma unroll
            for (int c = 0; c < 4; c++) acc[a][b][c] = 0.f;

    const int n0 = blockIdx.x * 128;
    const int m0 = blockIdx.y * 128;
    gemm_core_bf16s(g_aoh, g_aol, g_pwh, g_pwl, m0, n0, smu, acc, threadIdx.x);

    const int lane = threadIdx.x & 31, wid = threadIdx.x >> 5;
    const int g = lane >> 2, t = lane & 3;
    const int mw = (wid >> 1) * 32, nw = (wid & 1) * 64;

    float2 bias[8];
#pragma unroll
    for (int j = 0; j < 8; j++) {
        int n = n0 + nw + 8 * j + 2 * t;
        bias[j] = make_float2(pb[n], pb[n + 1]);
    }

#pragma unroll
    for (int mi = 0; mi < 2; mi++)
#pragma unroll
        for (int rr = 0; rr < 2; rr++) {
            int gm = m0 + mw + 16 * mi + g + 8 * rr;
            if (gm >= M_) continue;
            float* p = out + (size_t)gm * C_ + n0 + nw;
#pragma unroll
            for (int j = 0; j < 8; j++) {
                float2 o;
                o.x = acc[mi][j][2 * rr] + bias[j].x;
                o.y = acc[mi][j][2 * rr + 1] + bias[j].y;
                *(float2*)(p + 8 * j + 2 * t) = o;
            }
        }
}

// ---------------------------------------------------------------------------
// launch
// ---------------------------------------------------------------------------
extern "C" void kernel_launch(void* const* d_in, const int* in_sizes, int n_in,
                              void* d_out, int out_size)
{
    const float* x    = (const float*)d_in[0];
    const float* Wqkv = (const float*)d_in[1];
    const float* qb   = (const float*)d_in[2];
    const float* vb   = (const float*)d_in[3];
    const float* sml  = (const float*)d_in[4];
    const float* pW   = (const float*)d_in[5];
    const float* pb   = (const float*)d_in[6];
    const float* rope = (const float*)d_in[7];
    float* out = (float*)d_out;

    const size_t gemm_shm  = (size_t)2 * GSTAGE * sizeof(uint32_t);   // 98,304 B
    const size_t flash_shm = (size_t)2 * FSTAGE * sizeof(float);      // 137,216 B

    cudaFuncSetAttribute(qkv_gemm, cudaFuncAttributeMaxDynamicSharedMemorySize, (int)gemm_shm);
    cudaFuncSetAttribute(proj_gemm, cudaFuncAttributeMaxDynamicSharedMemorySize, (int)gemm_shm);
    cudaFuncSetAttribute(flash_attn, cudaFuncAttributeMaxDynamicSharedMemorySize, (int)flash_shm);

    {
        int np;
        np = M_ * KP_;    convert_split<<<(np + 255) / 256, 256>>>(x, 0, np);
        np = NQKV * KP_;  convert_split<<<(np + 255) / 256, 256>>>(Wqkv, 1, np);
        np = C_ * KP_;    convert_split<<<(np + 255) / 256, 256>>>(pW, 2, np);
    }

    dim3 g1(NQKV / 128, (M_ + 127) / 128);   // 48 x 40
    qkv_gemm<<<g1, 256, gemm_shm>>>(qb, vb);

    int nwarps = B_ * H_ * L_;
    norm_rope<<<(nwarps + 7) / 8, 256>>>(sml, rope);

    dim3 g3((L_ + 127) / 128, B_ * H_);      // 20 x 32
    flash_attn<<<g3, 256, flash_shm>>>();

    dim3 g4(C_ / 128, (M_ + 127) / 128);     // 16 x 40
    proj_gemm<<<g4, 256, gemm_shm>>>(pb, out);
}

// round 6
// speedup vs baseline: 2.3967x; 1.0542x over previous
#include <cuda_runtime.h>
#include <cuda_bf16.h>
#include <cstdint>
#include <math.h>

// ---------------------------------------------------------------------------
// Problem constants
// ---------------------------------------------------------------------------
#define B_   2
#define L_   2521
#define C_   2048
#define H_   16
#define HD_  128
#define M_   (B_ * L_)          // 5042
#define K_   2048
#define KP_  1024               // K/2 u32 pairs per row
#define NQKV 6144

__device__ __constant__ int d_cum[10] = {1, 5, 21, 57, 121, 265, 521, 921, 1497, 2521};

// f32 scratch; q/k stored d-PERMUTED (perm8 within 8-groups) and tf32-rounded,
// v stored plain d-order, tf32-rounded.
__device__ float g_q[B_ * H_ * L_ * HD_];
__device__ float g_k[B_ * H_ * L_ * HD_];
__device__ float g_v[B_ * H_ * L_ * HD_];

// split-bf16 scratch (u32 = packed bf16x2, pair-permuted layout)
__device__ uint32_t g_xh[M_ * KP_],   g_xl[M_ * KP_];
__device__ uint32_t g_wh[NQKV * KP_], g_wl[NQKV * KP_];
__device__ uint32_t g_pwh[C_ * KP_],  g_pwl[C_ * KP_];
__device__ uint32_t g_aoh[M_ * KP_],  g_aol[M_ * KP_];

// ---------------------------------------------------------------------------
// helpers
// ---------------------------------------------------------------------------
__device__ __forceinline__ uint32_t f2tf(float x) {
    uint32_t r;
    asm("cvt.rna.tf32.f32 %0, %1;" : "=r"(r) : "f"(x));
    return r;
}
__device__ __forceinline__ float tf32r(float x) { return __uint_as_float(f2tf(x)); }

__device__ __forceinline__ void mma8(float* c,
                                     uint32_t a0, uint32_t a1, uint32_t a2, uint32_t a3,
                                     uint32_t b0, uint32_t b1)
{
    asm volatile(
        "mma.sync.aligned.m16n8k8.row.col.f32.tf32.tf32.f32 "
        "{%0,%1,%2,%3}, {%4,%5,%6,%7}, {%8,%9}, {%0,%1,%2,%3};"
        : "+f"(c[0]), "+f"(c[1]), "+f"(c[2]), "+f"(c[3])
        : "r"(a0), "r"(a1), "r"(a2), "r"(a3), "r"(b0), "r"(b1));
}

__device__ __forceinline__ void mma16(float* c,
                                      uint32_t a0, uint32_t a1, uint32_t a2, uint32_t a3,
                                      uint32_t b0, uint32_t b1)
{
    asm volatile(
        "mma.sync.aligned.m16n8k16.row.col.f32.bf16.bf16.f32 "
        "{%0,%1,%2,%3}, {%4,%5,%6,%7}, {%8,%9}, {%0,%1,%2,%3};"
        : "+f"(c[0]), "+f"(c[1]), "+f"(c[2]), "+f"(c[3])
        : "r"(a0), "r"(a1), "r"(a2), "r"(a3), "r"(b0), "r"(b1));
}

__device__ __forceinline__ uint32_t smaddr(const void* p) {
    return (uint32_t)__cvta_generic_to_shared(p);
}
__device__ __forceinline__ void cp16(uint32_t dst, const void* src, bool pred) {
    int sz = pred ? 16 : 0;
    asm volatile("cp.async.cg.shared.global [%0], [%1], 16, %2;"
                 :: "r"(dst), "l"(src), "r"(sz));
}
__device__ __forceinline__ void cp_commit() {
    asm volatile("cp.async.commit_group;");
}
template<int N>
__device__ __forceinline__ void cp_wait() {
    asm volatile("cp.async.wait_group %0;" :: "n"(N));
}

// permuted pair column for split-bf16 GEMM fragments
__device__ __forceinline__ int pair_perm(int p) {
    int q = p & 15;
    return (p & ~15) + (q & 8) + (q & 3) * 2 + ((q >> 2) & 1);
}

__device__ __forceinline__ void split_pack(float x0, float x1, uint32_t& hp, uint32_t& lp) {
    __nv_bfloat16 h0 = __float2bfloat16_rn(x0);
    __nv_bfloat16 h1 = __float2bfloat16_rn(x1);
    float l0f = x0 - __bfloat162float(h0);
    float l1f = x1 - __bfloat162float(h1);
    __nv_bfloat16 l0 = __float2bfloat16_rn(l0f);
    __nv_bfloat16 l1 = __float2bfloat16_rn(l1f);
    hp = (uint32_t)__bfloat16_as_ushort(h0) | ((uint32_t)__bfloat16_as_ushort(h1) << 16);
    lp = (uint32_t)__bfloat16_as_ushort(l0) | ((uint32_t)__bfloat16_as_ushort(l1) << 16);
}

// ---------------------------------------------------------------------------
// Kernel 0: f32 -> split-bf16 pre-conversion (permuted layout)
// ---------------------------------------------------------------------------
__global__ void __launch_bounds__(256)
convert_split(const float* __restrict__ src, int which, int npairs)
{
    int i = blockIdx.x * 256 + threadIdx.x;
    if (i >= npairs) return;
    int row = i >> 10;
    int p = i & 1023;
    float2 v = *(const float2*)(src + (size_t)row * K_ + p * 2);
    uint32_t hp, lp;
    split_pack(v.x, v.y, hp, lp);
    int c = pair_perm(p);
    uint32_t* hi = (which == 0) ? g_xh : (which == 1) ? g_wh : g_pwh;
    uint32_t* lo = (which == 0) ? g_xl : (which == 1) ? g_wl : g_pwl;
    hi[(size_t)row * KP_ + c] = hp;
    lo[(size_t)row * KP_ + c] = lp;
}

// ---------------------------------------------------------------------------
// GEMM core: split-bf16, cp.async 3-stage, BK=32 (16 u32/row), XOR swizzle.
// physical word = logical ^ ((row & 3) << 2)  -> conflict-free uint2 frags.
// ---------------------------------------------------------------------------
#define GW 16
#define GARR (128 * GW)          // 2048 u32
#define GSTAGE (4 * GARR)        // 8192 u32 = 32 KB

__device__ __forceinline__ void gemm_prefetch(
    uint32_t* sbase, const uint32_t* agh, const uint32_t* agl,
    const uint32_t* bgh, const uint32_t* bgl, int ku, bool aok, int r, int fq)
{
    int sw = (r & 3) << 2;
    int w0 = ((fq ^ sw)) * 4;         // byte offsets of 16B chunks
    int w1 = (((fq + 4) ^ sw)) * 4;
    uint32_t dA = smaddr(sbase + r * GW);
    cp16(dA + w0, agh + ku,     aok);
    cp16(dA + w1, agh + ku + 4, aok);
    uint32_t dAl = dA + GARR * 4;
    cp16(dAl + w0, agl + ku,     aok);
    cp16(dAl + w1, agl + ku + 4, aok);
    uint32_t dB = dAl + GARR * 4;
    cp16(dB + w0, bgh + ku,     true);
    cp16(dB + w1, bgh + ku + 4, true);
    uint32_t dBl = dB + GARR * 4;
    cp16(dBl + w0, bgl + ku,     true);
    cp16(dBl + w1, bgl + ku + 4, true);
}

__device__ __forceinline__ void gemm_core_bf16s(
    const uint32_t* __restrict__ Ahg, const uint32_t* __restrict__ Alg,
    const uint32_t* __restrict__ Bhg, const uint32_t* __restrict__ Blg,
    int m0, int n0, uint32_t* sm, float acc[2][8][4], int tid)
{
    const int lane = tid & 31, wid = tid >> 5;
    const int g = lane >> 2, t = lane & 3;
    const int mw = (wid >> 1) * 32, nw = (wid & 1) * 64;

    const int r = tid >> 1;
    const int fq = (tid & 1) * 8;
    const bool aok = (m0 + r) < M_;
    const int arow = aok ? (m0 + r) : 0;
    const uint32_t* agh = Ahg + (size_t)arow * KP_ + fq;
    const uint32_t* agl = Alg + (size_t)arow * KP_ + fq;
    const uint32_t* bgh = Bhg + (size_t)(n0 + r) * KP_ + fq;
    const uint32_t* bgl = Blg + (size_t)(n0 + r) * KP_ + fq;

    gemm_prefetch(sm,              agh, agl, bgh, bgl, 0,  aok, r, fq);
    cp_commit();
    gemm_prefetch(sm + GSTAGE,     agh, agl, bgh, bgl, 16, aok, r, fq);
    cp_commit();

    const int swf = (g & 3) << 2;
    const int NIT = KP_ / 16;    // 64

    for (int it = 0; it < NIT; it++) {
        if (it + 1 >= NIT) cp_wait<0>(); else cp_wait<1>();
        __syncthreads();
        if (it + 2 < NIT) {
            gemm_prefetch(sm + ((it + 2) % 3) * GSTAGE, agh, agl, bgh, bgl,
                          (it + 2) * 16, aok, r, fq);
            cp_commit();
        }

        uint32_t* Ah = sm + (it % 3) * GSTAGE;
        uint32_t* Al = Ah + GARR;
        uint32_t* Bh = Al + GARR;
        uint32_t* Bl = Bh + GARR;

#pragma unroll
        for (int ks = 0; ks < 2; ks++) {
            const int wb = (ks * 8 + 2 * t) ^ swf;
            uint32_t ah[2][4], al[2][4];
#pragma unroll
            for (int mi = 0; mi < 2; mi++) {
                int r0 = mw + 16 * mi + g;
                uint2 v0 = *(uint2*)&Ah[r0 * GW + wb];
                uint2 v1 = *(uint2*)&Ah[(r0 + 8) * GW + wb];
                ah[mi][0] = v0.x; ah[mi][2] = v0.y;
                ah[mi][1] = v1.x; ah[mi][3] = v1.y;
                uint2 w0 = *(uint2*)&Al[r0 * GW + wb];
                uint2 w1 = *(uint2*)&Al[(r0 + 8) * GW + wb];
                al[mi][0] = w0.x; al[mi][2] = w0.y;
                al[mi][1] = w1.x; al[mi][3] = w1.y;
            }
#pragma unroll
            for (int j = 0; j < 8; j++) {
                int cn = nw + 8 * j + g;
                uint2 bh = *(uint2*)&Bh[cn * GW + wb];
                uint2 bl = *(uint2*)&Bl[cn * GW + wb];
#pragma unroll
                for (int mi = 0; mi < 2; mi++) {
                    mma16(acc[mi][j], ah[mi][0], ah[mi][1], ah[mi][2], ah[mi][3], bh.x, bh.y);
                    mma16(acc[mi][j], ah[mi][0], ah[mi][1], ah[mi][2], ah[mi][3], bl.x, bl.y);
                    mma16(acc[mi][j], al[mi][0], al[mi][1], al[mi][2], al[mi][3], bh.x, bh.y);
                }
            }
        }
    }
}

// ---------------------------------------------------------------------------
// Kernel 1: QKV GEMM + scatter epilogue.
// q/k written with d-permutation perm8 (col c -> (c&~7) + (c&3)*2 + (c>>2&1))
// and tf32-rounded; v plain order, tf32-rounded.
// ---------------------------------------------------------------------------
__global__ void __launch_bounds__(256, 2)
qkv_gemm(const float* __restrict__ qb, const float* __restrict__ vb)
{
    extern __shared__ uint32_t smu[];
    float acc[2][8][4];
#pragma unroll
    for (int a = 0; a < 2; a++)
#pragma unroll
        for (int b = 0; b < 8; b++)
#pragma unroll
            for (int c = 0; c < 4; c++) acc[a][b][c] = 0.f;

    const int n0 = blockIdx.x * 128;
    const int m0 = blockIdx.y * 128;
    gemm_core_bf16s(g_xh, g_xl, g_wh, g_wl, m0, n0, smu, acc, threadIdx.x);

    const int lane = threadIdx.x & 31, wid = threadIdx.x >> 5;
    const int g = lane >> 2, t = lane & 3;
    const int mw = (wid >> 1) * 32, nw = (wid & 1) * 64;

    const int tq = n0 >> 11;
    const int h = (n0 & 2047) >> 7;
    float* dst = (tq == 0) ? g_q : ((tq == 1) ? g_k : g_v);

    float2 bias[8];
#pragma unroll
    for (int j = 0; j < 8; j++) {
        int d = nw + 8 * j + 2 * t;
        float b0 = 0.f, b1 = 0.f;
        if (tq == 0) { b0 = qb[h * HD_ + d]; b1 = qb[h * HD_ + d + 1]; }
        else if (tq == 2) { b0 = vb[h * HD_ + d]; b1 = vb[h * HD_ + d + 1]; }
        bias[j] = make_float2(b0, b1);
    }

    const int sl0 = 4 * (t & 1) + (t >> 1);   // perm8(2t); perm8(2t+1) = sl0+2

#pragma unroll
    for (int mi = 0; mi < 2; mi++)
#pragma unroll
        for (int rr = 0; rr < 2; rr++) {
            int gm = m0 + mw + 16 * mi + g + 8 * rr;
            if (gm >= M_) continue;
            int b = gm / L_;
            int l = gm - b * L_;
            float* p = dst + ((size_t)(b * H_ + h) * L_ + l) * HD_;
#pragma unroll
            for (int j = 0; j < 8; j++) {
                float ox = acc[mi][j][2 * rr] + bias[j].x;
                float oy = acc[mi][j][2 * rr + 1] + bias[j].y;
                if (tq == 2) {
                    float2 o = make_float2(tf32r(ox), tf32r(oy));
                    *(float2*)(p + nw + 8 * j + 2 * t) = o;
                } else {
                    int dg = nw + 8 * j;
                    p[dg + sl0]     = ox;
                    p[dg + sl0 + 2] = oy;
                }
            }
        }
}

// ---------------------------------------------------------------------------
// Kernel 2: norm + rope on PERMUTED q/k storage; outputs tf32-rounded.
// lane handles original cols 4l..4l+3 = slots base+{0,2,4,6}, base = (l>>1)*8 + (l&1)
// ---------------------------------------------------------------------------
__global__ void __launch_bounds__(256)
norm_rope(const float* __restrict__ sml, const float* __restrict__ rope)
{
    const int gw = blockIdx.x * 8 + (threadIdx.x >> 5);
    const int lane = threadIdx.x & 31;
    if (gw >= B_ * H_ * L_) return;
    const int l = gw % L_;
    const int h = (gw / L_) % H_;

    float2 cc = *(const float2*)(rope + (size_t)l * 64 + lane * 2);
    float2 ss = *(const float2*)(rope + (size_t)L_ * 64 + (size_t)l * 64 + lane * 2);
    const float scale = __expf(fminf(sml[h], 4.605170185988091f));
    const size_t base = (size_t)gw * HD_ + (lane >> 1) * 8 + (lane & 1);

    {
        float v0 = g_q[base], v1 = g_q[base + 2], v2 = g_q[base + 4], v3 = g_q[base + 6];
        float ssq = v0 * v0 + v1 * v1 + v2 * v2 + v3 * v3;
#pragma unroll
        for (int o = 16; o; o >>= 1) ssq += __shfl_xor_sync(0xffffffffu, ssq, o);
        float inv = scale / fmaxf(sqrtf(ssq), 1e-12f);
        v0 *= inv; v1 *= inv; v2 *= inv; v3 *= inv;
        g_q[base]     = tf32r(cc.x * v0 - ss.x * v1);
        g_q[base + 2] = tf32r(ss.x * v0 + cc.x * v1);
        g_q[base + 4] = tf32r(cc.y * v2 - ss.y * v3);
        g_q[base + 6] = tf32r(ss.y * v2 + cc.y * v3);
    }
    {
        float v0 = g_k[base], v1 = g_k[base + 2], v2 = g_k[base + 4], v3 = g_k[base + 6];
        float ssq = v0 * v0 + v1 * v1 + v2 * v2 + v3 * v3;
#pragma unroll
        for (int o = 16; o; o >>= 1) ssq += __shfl_xor_sync(0xffffffffu, ssq, o);
        float inv = 1.f / fmaxf(sqrtf(ssq), 1e-12f);
        v0 *= inv; v1 *= inv; v2 *= inv; v3 *= inv;
        g_k[base]     = tf32r(cc.x * v0 - ss.x * v1);
        g_k[base + 2] = tf32r(ss.x * v0 + cc.x * v1);
        g_k[base + 4] = tf32r(cc.y * v2 - ss.y * v3);
        g_k[base + 6] = tf32r(ss.y * v2 + cc.y * v3);
    }
}

// ---------------------------------------------------------------------------
// Kernel 3: flash attention. Pitch-128 rows with XOR swizzle (row&3)<<3.
// Q/K d-permuted -> S frags are uint2 loads. V row-permuted at copy so P stays
// in registers. 3-stage cp.async K/V pipeline, one sync per iter.
// ---------------------------------------------------------------------------
#define FW 128
#define FKB (64 * FW)             // 8192 floats per K (or V) tile
#define FSTG (2 * FKB)            // 16384 floats = 64 KB per stage

__device__ __forceinline__ int kend_of(int lq) {
    if (lq >= L_) return 0;
    int ke = 2521;
#pragma unroll
    for (int i = 9; i >= 0; i--)
        if (lq < d_cum[i]) ke = d_cum[i];
    return ke;
}

__device__ __forceinline__ void flash_prefetch(
    float* sm, int s, int k0, const float* kp, const float* vp, int tid)
{
    float* Kb = sm + s * FSTG;
    float* Vb = Kb + FKB;
    int kr = tid >> 2;
    int cb = (tid & 3) * 32;
    bool ok = (k0 + kr) < L_;
    const float* ks = kp + (size_t)(ok ? (k0 + kr) : 0) * HD_ + cb;
    int swk = (kr & 3) << 3;
    uint32_t dK = smaddr(Kb + kr * FW);
#pragma unroll
    for (int i = 0; i < 8; i++)
        cp16(dK + 4 * ((cb + 4 * i) ^ swk), ks + 4 * i, ok);
    // V key-slot permutation: key k -> slot (k>>1) + ((k&1)<<2) within 8-group
    int w = kr & 7;
    int slot = (kr & ~7) + (w >> 1) + ((w & 1) << 2);
    int swv = (slot & 3) << 3;
    const float* vs = vp + (size_t)(ok ? (k0 + kr) : 0) * HD_ + cb;
    uint32_t dV = smaddr(Vb + slot * FW);
#pragma unroll
    for (int i = 0; i < 8; i++)
        cp16(dV + 4 * ((cb + 4 * i) ^ swv), vs + 4 * i, ok);
}

__global__ void __launch_bounds__(256, 1)
flash_attn()
{
    extern __shared__ float sm[];

    const int bh = blockIdx.y;
    const int q0 = (gridDim.x - 1 - blockIdx.x) * 128;
    const float* qp = g_q + (size_t)bh * L_ * HD_;
    const float* kp = g_k + (size_t)bh * L_ * HD_;
    const float* vp = g_v + (size_t)bh * L_ * HD_;
    const int tid = threadIdx.x, lane = tid & 31, wid = tid >> 5;
    const int g = lane >> 2, t = lane & 3;
    const int rowbase = wid * 16 + g;
    const int swg = (g & 3) << 3;

    int kmax;
    {
        int lql = min(q0 + 127, L_ - 1);
        kmax = 2521;
#pragma unroll
        for (int i = 9; i >= 0; i--)
            if (lql < d_cum[i]) kmax = d_cum[i];
    }
    const int niter = (kmax + 63) / 64;

    // stage Q (stage-0 area), overlap tile0/tile1 K/V loads with extraction
    {
        int r = tid >> 1;
        int cb = (tid & 1) * 64;
        bool ok = (q0 + r) < L_;
        const float* src = qp + (size_t)(ok ? (q0 + r) : 0) * HD_ + cb;
        int sw = (r & 3) << 3;
        uint32_t d = smaddr(sm + r * FW);
#pragma unroll
        for (int i = 0; i < 16; i++)
            cp16(d + 4 * ((cb + 4 * i) ^ sw), src + 4 * i, ok);
    }
    cp_commit();
    flash_prefetch(sm, 1, 0, kp, vp, tid);
    cp_commit();
    if (niter > 1) flash_prefetch(sm, 2, 64, kp, vp, tid);
    cp_commit();

    cp_wait<2>();        // Q landed; tile0/1 still in flight
    __syncthreads();

    uint32_t qf[16][4];
#pragma unroll
    for (int kk8 = 0; kk8 < 16; kk8++) {
        int wb = (kk8 * 8 + 2 * t) ^ swg;
        uint2 a0 = *(const uint2*)&sm[rowbase * FW + wb];
        uint2 a1 = *(const uint2*)&sm[(rowbase + 8) * FW + wb];
        qf[kk8][0] = a0.x; qf[kk8][2] = a0.y;
        qf[kk8][1] = a1.x; qf[kk8][3] = a1.y;
    }
    __syncthreads();

    const int kend0 = kend_of(q0 + rowbase);
    const int kend1 = kend_of(q0 + rowbase + 8);

    float m0v = -1e30f, m1v = -1e30f, l0v = 0.f, l1v = 0.f;
    float O[16][4];
#pragma unroll
    for (int j = 0; j < 16; j++)
#pragma unroll
        for (int c = 0; c < 4; c++) O[j][c] = 0.f;

    for (int it = 0; it < niter; it++) {
        const int k0 = it * 64;
        if (it + 1 >= niter) cp_wait<0>(); else cp_wait<1>();
        __syncthreads();
        if (it + 2 < niter) {
            flash_prefetch(sm, it % 3, (it + 2) * 64, kp, vp, tid);
            cp_commit();
        }

        float* Kb = sm + ((it + 1) % 3) * FSTG;
        float* Vb = Kb + FKB;

        // S = Q K^T
        float sc[8][4];
#pragma unroll
        for (int j = 0; j < 8; j++)
#pragma unroll
            for (int c = 0; c < 4; c++) sc[j][c] = 0.f;

#pragma unroll
        for (int kk8 = 0; kk8 < 16; kk8++) {
            int wb = (kk8 * 8 + 2 * t) ^ swg;
#pragma unroll
            for (int j = 0; j < 8; j++) {
                uint2 bb = *(const uint2*)&Kb[(8 * j + g) * FW + wb];
                mma8(sc[j], qf[kk8][0], qf[kk8][1], qf[kk8][2], qf[kk8][3], bb.x, bb.y);
            }
        }

        // mask + online softmax
        float rmax0 = -1e30f, rmax1 = -1e30f;
#pragma unroll
        for (int j = 0; j < 8; j++) {
            int c0 = k0 + 8 * j + 2 * t, c1 = c0 + 1;
            if (c0 >= kend0) sc[j][0] = -1e30f;
            if (c1 >= kend0) sc[j][1] = -1e30f;
            if (c0 >= kend1) sc[j][2] = -1e30f;
            if (c1 >= kend1) sc[j][3] = -1e30f;
            rmax0 = fmaxf(rmax0, fmaxf(sc[j][0], sc[j][1]));
            rmax1 = fmaxf(rmax1, fmaxf(sc[j][2], sc[j][3]));
        }
        rmax0 = fmaxf(rmax0, __shfl_xor_sync(0xffffffffu, rmax0, 1));
        rmax0 = fmaxf(rmax0, __shfl_xor_sync(0xffffffffu, rmax0, 2));
        rmax1 = fmaxf(rmax1, __shfl_xor_sync(0xffffffffu, rmax1, 1));
        rmax1 = fmaxf(rmax1, __shfl_xor_sync(0xffffffffu, rmax1, 2));

        float mn0 = fmaxf(m0v, rmax0), mn1 = fmaxf(m1v, rmax1);
        float al0 = __expf(m0v - mn0), al1 = __expf(m1v - mn1);
        float rs0 = 0.f, rs1 = 0.f;
#pragma unroll
        for (int j = 0; j < 8; j++) {
            float p0 = (sc[j][0] > -5e29f) ? __expf(sc[j][0] - mn0) : 0.f;
            float p1 = (sc[j][1] > -5e29f) ? __expf(sc[j][1] - mn0) : 0.f;
            float p2 = (sc[j][2] > -5e29f) ? __expf(sc[j][2] - mn1) : 0.f;
            float p3 = (sc[j][3] > -5e29f) ? __expf(sc[j][3] - mn1) : 0.f;
            rs0 += p0 + p1;
            rs1 += p2 + p3;
            sc[j][0] = p0; sc[j][1] = p1; sc[j][2] = p2; sc[j][3] = p3;
        }
        rs0 += __shfl_xor_sync(0xffffffffu, rs0, 1);
        rs0 += __shfl_xor_sync(0xffffffffu, rs0, 2);
        rs1 += __shfl_xor_sync(0xffffffffu, rs1, 1);
        rs1 += __shfl_xor_sync(0xffffffffu, rs1, 2);
        l0v = l0v * al0 + rs0;
        l1v = l1v * al1 + rs1;
        m0v = mn0; m1v = mn1;

#pragma unroll
        for (int j = 0; j < 16; j++) {
            O[j][0] *= al0; O[j][1] *= al0;
            O[j][2] *= al1; O[j][3] *= al1;
        }

        // O += P V  (P from sc regs; V slot-permuted rows)
        const int swv = t << 3;
#pragma unroll
        for (int c = 0; c < 8; c++) {
            uint32_t a0 = f2tf(sc[c][0]);
            uint32_t a1 = f2tf(sc[c][2]);
            uint32_t a2 = f2tf(sc[c][1]);
            uint32_t a3 = f2tf(sc[c][3]);
            const float* v0 = Vb + (8 * c + t) * FW;
            const float* v1 = Vb + (8 * c + t + 4) * FW;
#pragma unroll
            for (int j = 0; j < 16; j++) {
                int wv = (g + 8 * j) ^ swv;
                uint32_t b0 = __float_as_uint(v0[wv]);
                uint32_t b1 = __float_as_uint(v1[wv]);
                mma8(O[j], a0, a1, a2, a3, b0, b1);
            }
        }
    }

    // epilogue: normalize, convert to split-bf16 pairs, write permuted layout
    const int b = bh >> 4;
    const int h = bh & 15;
#pragma unroll
    for (int rr = 0; rr < 2; rr++) {
        int lq = q0 + rowbase + 8 * rr;
        if (lq >= L_) continue;
        float inv = 1.f / (rr ? l1v : l0v);
        size_t rowoff = (size_t)(b * L_ + lq) * KP_;
#pragma unroll
        for (int j = 0; j < 16; j++) {
            float x0 = O[j][2 * rr] * inv;
            float x1 = O[j][2 * rr + 1] * inv;
            uint32_t hp, lp;
            split_pack(x0, x1, hp, lp);
            int p = h * 64 + 4 * j + t;
            int c = pair_perm(p);
            g_aoh[rowoff + c] = hp;
            g_aol[rowoff + c] = lp;
        }
    }
}

// ---------------------------------------------------------------------------
// Kernel 4: projection GEMM
// ---------------------------------------------------------------------------
__global__ void __launch_bounds__(256, 2)
proj_gemm(const float* __restrict__ pb, float* __restrict__ out)
{
    extern __shared__ uint32_t smu[];
    float acc[2][8][4];
#pragma unroll
    for (int a = 0; a < 2; a++)
#pragma unroll
        for (int b = 0; b < 8; b++)
#pragma unroll
            for (int c = 0; c < 4; c++) acc[a][b][c] = 0.f;

    const int n0 = blockIdx.x * 128;
    const int m0 = blockIdx.y * 128;
    gemm_core_bf16s(g_aoh, g_aol, g_pwh, g_pwl, m0, n0, smu, acc, threadIdx.x);

    const int lane = threadIdx.x & 31, wid = threadIdx.x >> 5;
    const int g = lane >> 2, t = lane & 3;
    const int mw = (wid >> 1) * 32, nw = (wid & 1) * 64;

    float2 bias[8];
#pragma unroll
    for (int j = 0; j < 8; j++) {
        int n = n0 + nw + 8 * j + 2 * t;
        bias[j] = make_float2(pb[n], pb[n + 1]);
    }

#pragma unroll
    for (int mi = 0; mi < 2; mi++)
#pragma unroll
        for (int rr = 0; rr < 2; rr++) {
            int gm = m0 + mw + 16 * mi + g + 8 * rr;
            if (gm >= M_) continue;
            float* p = out + (size_t)gm * C_ + n0 + nw;
#pragma unroll
            for (int j = 0; j < 8; j++) {
                float2 o;
                o.x = acc[mi][j][2 * rr] + bias[j].x;
                o.y = acc[mi][j][2 * rr + 1] + bias[j].y;
                *(float2*)(p + 8 * j + 2 * t) = o;
            }
        }
}

// ---------------------------------------------------------------------------
// launch
// ---------------------------------------------------------------------------
extern "C" void kernel_launch(void* const* d_in, const int* in_sizes, int n_in,
                              void* d_out, int out_size)
{
    const float* x    = (const float*)d_in[0];
    const float* Wqkv = (const float*)d_in[1];
    const float* qb   = (const float*)d_in[2];
    const float* vb   = (const float*)d_in[3];
    const float* sml  = (const float*)d_in[4];
    const float* pW   = (const float*)d_in[5];
    const float* pb   = (const float*)d_in[6];
    const float* rope = (const float*)d_in[7];
    float* out = (float*)d_out;

    const size_t gemm_shm  = (size_t)3 * GSTAGE * sizeof(uint32_t);   // 98,304 B
    const size_t flash_shm = (size_t)3 * FSTG * sizeof(float);        // 196,608 B

    cudaFuncSetAttribute(qkv_gemm, cudaFuncAttributeMaxDynamicSharedMemorySize, (int)gemm_shm);
    cudaFuncSetAttribute(proj_gemm, cudaFuncAttributeMaxDynamicSharedMemorySize, (int)gemm_shm);
    cudaFuncSetAttribute(flash_attn, cudaFuncAttributeMaxDynamicSharedMemorySize, (int)flash_shm);

    {
        int np;
        np = M_ * KP_;    convert_split<<<(np + 255) / 256, 256>>>(x, 0, np);
        np = NQKV * KP_;  convert_split<<<(np + 255) / 256, 256>>>(Wqkv, 1, np);
        np = C_ * KP_;    convert_split<<<(np + 255) / 256, 256>>>(pW, 2, np);
    }

    dim3 g1(NQKV / 128, (M_ + 127) / 128);   // 48 x 40
    qkv_gemm<<<g1, 256, gemm_shm>>>(qb, vb);

    int nwarps = B_ * H_ * L_;
    norm_rope<<<(nwarps + 7) / 8, 256>>>(sml, rope);

    dim3 g3((L_ + 127) / 128, B_ * H_);      // 20 x 32
    flash_attn<<<g3, 256, flash_shm>>>();

    dim3 g4(C_ / 128, (M_ + 127) / 128);     // 16 x 40
    proj_gemm<<<g4, 256, gemm_shm>>>(pb, out);
}